// round 1
// baseline (speedup 1.0000x reference)
#include <cuda_runtime.h>
#include <cuda_bf16.h>
#include <math.h>

// ---------------------------------------------------------------------------
// Problem constants
// ---------------------------------------------------------------------------
constexpr int Bq = 8, Lq = 12, Nn = 207, Dm = 512, Hh = 8, Ff = 2048;
constexpr int Ol = 12, NGc = 3;
constexpr int T  = Lq * Nn;          // 2484
constexpr int MT = Bq * T;           // 19872 rows
constexpr int E  = Dm / Hh;          // 64
constexpr int CC = Dm * (NGc + 1) * 2 + Dm;  // 4608

constexpr size_t MTD = (size_t)MT * Dm;        // 10,174,464
constexpr size_t OFF_Q    = 0;
constexpr size_t OFF_K    = 1 * MTD;
constexpr size_t OFF_V    = 2 * MTD;
constexpr size_t OFF_ATTN = 3 * MTD;
constexpr size_t OFF_H    = 4 * MTD;
constexpr size_t OFF_Y    = 5 * MTD;
constexpr size_t OFF_MEM  = 6 * MTD;
constexpr size_t OFF_SOUT = 7 * MTD;
constexpr size_t OFF_FFN  = 8 * MTD;                       // MT*Ff = 4*MTD
constexpr size_t OFF_KV   = 12 * MTD;                      // 64*4096
constexpr size_t OFF_KSUM = OFF_KV + (size_t)Bq * Hh * E * E;
constexpr size_t OFF_S2   = OFF_KSUM + (size_t)Bq * Hh * E;
constexpr size_t OFF_CAT  = OFF_S2 + (size_t)Bq * Lq * Nn * Nn;
constexpr size_t OFF_TSWT = OFF_CAT + (size_t)Bq * Ol * CC * Nn;
constexpr size_t OFF_ADJ  = OFF_TSWT + (size_t)Dm * Nn;
constexpr size_t OFF_SCALE= OFF_ADJ + (size_t)NGc * Nn * Nn;
constexpr size_t OFF_SHIFT= OFF_SCALE + (size_t)Ol * Dm;
constexpr size_t TOTAL    = OFF_SHIFT + (size_t)Ol * Dm;

__device__ __align__(16) float g_buf[TOTAL];

// ---------------------------------------------------------------------------
// Generic batched SGEMM: C = epi(A@B).  A: MxK (lda), B: KxN (ldb), row-major.
// Per-batch bases: ptr + (bz % mod) * stride.
// EPI: 0 none | 1 +bias[n] | 2 +bias[n],elu+1 | 3 +bias[n],gelu(tanh)
//      4 +bias[n]+res[m,n] | 5 val*P1[m]+P2[m], store C[n*ldc+m]
// ---------------------------------------------------------------------------
constexpr int TM = 128, TN = 128, TK = 8;

template <int EPI>
__global__ void __launch_bounds__(256)
gemm_k(const float* __restrict__ A, int lda, size_t sA, int mA,
       const float* __restrict__ Bm, int ldb, size_t sB, int mB,
       float* __restrict__ C, int ldc, size_t sC,
       const float* __restrict__ P1, size_t sP1, int mP1,
       const float* __restrict__ P2, size_t sP2, int mP2,
       int M, int N, int K)
{
    int bz = blockIdx.z;
    A  += (size_t)(bz % mA) * sA;
    Bm += (size_t)(bz % mB) * sB;
    C  += (size_t)bz * sC;
    const float* p1 = (EPI > 0) ? P1 + (size_t)(bz % mP1) * sP1 : nullptr;
    const float* p2 = (EPI == 4 || EPI == 5) ? P2 + (size_t)(bz % mP2) * sP2 : nullptr;

    __shared__ float As[TK][132];   // padded: conflict-free stores
    __shared__ float Bs[TK][TN];

    int tid = threadIdx.x;
    int tx = tid & 15, ty = tid >> 4;
    int m0 = blockIdx.y * TM;
    int n0 = blockIdx.x * TN;

    float acc[8][8] = {};

    for (int k0 = 0; k0 < K; k0 += TK) {
#pragma unroll
        for (int i = 0; i < 4; i++) {
            int idx = tid + i * 256;
            int mm = idx >> 3, kk = idx & 7;
            int gm = m0 + mm, gk = k0 + kk;
            As[kk][mm] = (gm < M && gk < K) ? A[(size_t)gm * lda + gk] : 0.f;
        }
#pragma unroll
        for (int i = 0; i < 4; i++) {
            int idx = tid + i * 256;
            int kk = idx >> 7, nn = idx & 127;
            int gk = k0 + kk, gn = n0 + nn;
            Bs[kk][nn] = (gk < K && gn < N) ? Bm[(size_t)gk * ldb + gn] : 0.f;
        }
        __syncthreads();
#pragma unroll
        for (int kk = 0; kk < TK; kk++) {
            float4 a0 = *(const float4*)&As[kk][ty * 8];
            float4 a1 = *(const float4*)&As[kk][ty * 8 + 4];
            float4 b0 = *(const float4*)&Bs[kk][tx * 8];
            float4 b1 = *(const float4*)&Bs[kk][tx * 8 + 4];
            float a[8] = {a0.x, a0.y, a0.z, a0.w, a1.x, a1.y, a1.z, a1.w};
            float b[8] = {b0.x, b0.y, b0.z, b0.w, b1.x, b1.y, b1.z, b1.w};
#pragma unroll
            for (int i = 0; i < 8; i++)
#pragma unroll
                for (int j = 0; j < 8; j++)
                    acc[i][j] = fmaf(a[i], b[j], acc[i][j]);
        }
        __syncthreads();
    }

#pragma unroll
    for (int i = 0; i < 8; i++) {
        int m = m0 + ty * 8 + i;
        if (m >= M) continue;
#pragma unroll
        for (int j = 0; j < 8; j++) {
            int n = n0 + tx * 8 + j;
            if (n >= N) continue;
            float v = acc[i][j];
            if (EPI >= 1 && EPI <= 4) v += p1[n];
            if (EPI == 2) v = (v > 0.f) ? v + 1.f : expf(v);   // elu(x)+1
            if (EPI == 3) {
                float c = v * v * v;
                v = 0.5f * v * (1.f + tanhf(0.7978845608028654f * (v + 0.044715f * c)));
            }
            if (EPI == 4) v += p2[(size_t)m * ldc + n];
            if (EPI == 5) {
                v = v * p1[m] + p2[m];
                C[(size_t)n * ldc + m] = v;
            } else {
                C[(size_t)m * ldc + n] = v;
            }
        }
    }
}

template <int EPI>
static void launch_gemm(const float* A, int lda, size_t sA, int mA,
                        const float* B, int ldb, size_t sB, int mB,
                        float* C, int ldc, size_t sC,
                        const float* P1, size_t sP1, int mP1,
                        const float* P2, size_t sP2, int mP2,
                        int M, int N, int K, int batch)
{
    dim3 grid((N + TN - 1) / TN, (M + TM - 1) / TM, batch);
    gemm_k<EPI><<<grid, 256>>>(A, lda, sA, mA, B, ldb, sB, mB, C, ldc, sC,
                               P1, sP1, mP1, P2, sP2, mP2, M, N, K);
}

// ---------------------------------------------------------------------------
// Linear attention internals
// kv[b,h,e,d] = sum_t kf[t,e]*v[t,d];  ksum[b,h,e] = sum_t kf[t,e]
// One block per (b,h); deterministic (no atomics).
// ---------------------------------------------------------------------------
__global__ void __launch_bounds__(256)
kv_k(const float* __restrict__ kf, const float* __restrict__ vv,
     float* __restrict__ kv, float* __restrict__ ksum)
{
    int bh = blockIdx.x;
    int b = bh >> 3, h = bh & 7;
    const float* kbase = kf + (size_t)b * T * Dm + h * E;
    const float* vbase = vv + (size_t)b * T * Dm + h * E;
    __shared__ float ks[16][64];
    __shared__ float vs[16][64];
    int tid = threadIdx.x;
    int tx = tid & 15, ty = tid >> 4;
    float acc[4][4] = {};
    float csum = 0.f;
    for (int t0 = 0; t0 < T; t0 += 16) {
#pragma unroll
        for (int i = 0; i < 4; i++) {
            int idx = tid + i * 256;
            int rr = idx >> 6, cc = idx & 63;
            int gt = t0 + rr;
            bool ok = gt < T;
            ks[rr][cc] = ok ? kbase[(size_t)gt * Dm + cc] : 0.f;
            vs[rr][cc] = ok ? vbase[(size_t)gt * Dm + cc] : 0.f;
        }
        __syncthreads();
#pragma unroll
        for (int r = 0; r < 16; r++) {
            float a[4], bb[4];
#pragma unroll
            for (int i = 0; i < 4; i++) a[i] = ks[r][tx * 4 + i];
#pragma unroll
            for (int j = 0; j < 4; j++) bb[j] = vs[r][ty * 4 + j];
#pragma unroll
            for (int i = 0; i < 4; i++)
#pragma unroll
                for (int j = 0; j < 4; j++)
                    acc[i][j] = fmaf(a[i], bb[j], acc[i][j]);
        }
        if (tid < 64) {
#pragma unroll
            for (int r = 0; r < 16; r++) csum += ks[r][tid];
        }
        __syncthreads();
    }
    float* kvb = kv + (size_t)bh * E * E;
#pragma unroll
    for (int i = 0; i < 4; i++)
#pragma unroll
        for (int j = 0; j < 4; j++)
            kvb[(tx * 4 + i) * E + ty * 4 + j] = acc[i][j];
    if (tid < 64) ksum[(size_t)bh * E + tid] = csum;
}

// o[b,t,h,d] = (sum_e qf[t,e]*kv[e,d]) / (sum_e qf[t,e]*ksum[e] + eps)
__global__ void __launch_bounds__(256)
attn_o_k(const float* __restrict__ qf, const float* __restrict__ kv,
         const float* __restrict__ ksum, float* __restrict__ out)
{
    int bh = blockIdx.x;
    int b = bh >> 3, h = bh & 7;
    int t0 = blockIdx.y * 64;
    const float* qbase = qf + (size_t)b * T * Dm + h * E;
    __shared__ float qs[64][64];
    __shared__ float kvs[64][65];
    __shared__ float kss[64];
    __shared__ float zs[64];
    int tid = threadIdx.x;
    int tx = tid & 15, ty = tid >> 4;
#pragma unroll
    for (int i = 0; i < 16; i++) {
        int idx = tid + i * 256;
        int r = idx >> 6, c = idx & 63;
        kvs[r][c] = kv[(size_t)bh * E * E + idx];
        int gt = t0 + r;
        qs[r][c] = (gt < T) ? qbase[(size_t)gt * Dm + c] : 0.f;
    }
    if (tid < 64) kss[tid] = ksum[(size_t)bh * E + tid];
    __syncthreads();
    if (tid < 64) {
        float s = 0.f;
#pragma unroll
        for (int e = 0; e < 64; e++) s = fmaf(qs[tid][e], kss[e], s);
        zs[tid] = 1.f / (s + 1e-6f);
    }
    __syncthreads();
    float acc[4][4] = {};
#pragma unroll
    for (int e = 0; e < 64; e++) {
        float a[4], bb[4];
#pragma unroll
        for (int i = 0; i < 4; i++) a[i] = qs[ty * 4 + i][e];
#pragma unroll
        for (int j = 0; j < 4; j++) bb[j] = kvs[e][tx * 4 + j];
#pragma unroll
        for (int i = 0; i < 4; i++)
#pragma unroll
            for (int j = 0; j < 4; j++)
                acc[i][j] = fmaf(a[i], bb[j], acc[i][j]);
    }
#pragma unroll
    for (int i = 0; i < 4; i++) {
        int t = t0 + ty * 4 + i;
        if (t >= T) continue;
        float z = zs[ty * 4 + i];
#pragma unroll
        for (int j = 0; j < 4; j++)
            out[((size_t)b * T + t) * Dm + h * E + tx * 4 + j] = acc[i][j] * z;
    }
}

// ---------------------------------------------------------------------------
// LayerNorm over D=512, one block per row (128 threads, float4)
// ---------------------------------------------------------------------------
__global__ void __launch_bounds__(128)
ln_k(const float* __restrict__ x, const float* __restrict__ g,
     const float* __restrict__ bvec, float* __restrict__ out)
{
    int r = blockIdx.x;
    int t = threadIdx.x;
    const float4* xr = (const float4*)(x + (size_t)r * Dm);
    float4 v = xr[t];
    float s = v.x + v.y + v.z + v.w;
    float q = v.x * v.x + v.y * v.y + v.z * v.z + v.w * v.w;
#pragma unroll
    for (int o = 16; o > 0; o >>= 1) {
        s += __shfl_down_sync(0xffffffffu, s, o);
        q += __shfl_down_sync(0xffffffffu, q, o);
    }
    __shared__ float ss[4], qq[4], mv[2];
    int w = t >> 5, l = t & 31;
    if (l == 0) { ss[w] = s; qq[w] = q; }
    __syncthreads();
    if (t == 0) {
        float S = ss[0] + ss[1] + ss[2] + ss[3];
        float Q = qq[0] + qq[1] + qq[2] + qq[3];
        float m = S * (1.f / 512.f);
        float var = Q * (1.f / 512.f) - m * m;
        mv[0] = m;
        mv[1] = rsqrtf(var + 1e-5f);
    }
    __syncthreads();
    float m = mv[0], inv = mv[1];
    float4 gg = ((const float4*)g)[t];
    float4 bb = ((const float4*)bvec)[t];
    float4 o4;
    o4.x = (v.x - m) * inv * gg.x + bb.x;
    o4.y = (v.y - m) * inv * gg.y + bb.y;
    o4.z = (v.z - m) * inv * gg.z + bb.z;
    o4.w = (v.w - m) * inv * gg.w + bb.w;
    ((float4*)(out + (size_t)r * Dm))[t] = o4;
}

// ---------------------------------------------------------------------------
// tt: xg[b,o,d,n] = sum_l tt_w[o,l]*t_out[b,l,n,d] + tt_b[o]  → cat slice 0
// one block per (b,n)
// ---------------------------------------------------------------------------
__global__ void __launch_bounds__(256)
tt_k(const float* __restrict__ tout, const float* __restrict__ ttw,
     const float* __restrict__ ttb, float* __restrict__ cat)
{
    int bn = blockIdx.x;
    int b = bn / Nn, n = bn % Nn;
    __shared__ float xs[12][512];
    __shared__ float w[144];
    int tid = threadIdx.x;
    if (tid < 144) w[tid] = ttw[tid];
    for (int l = 0; l < 12; l++)
        for (int d = tid; d < 512; d += 256)
            xs[l][d] = tout[(((size_t)b * Lq + l) * Nn + n) * Dm + d];
    __syncthreads();
    for (int od = tid; od < 12 * 512; od += 256) {
        int o = od >> 9, d = od & 511;
        float s = ttb[o];
#pragma unroll
        for (int l = 0; l < 12; l++) s = fmaf(w[o * 12 + l], xs[l][d], s);
        cat[(((size_t)b * Ol + o) * CC + d) * Nn + n] = s;
    }
}

// ---------------------------------------------------------------------------
// Small prep kernels
// ---------------------------------------------------------------------------
__global__ void prep_tswT(const float* __restrict__ tsw, float* __restrict__ outT)
{
    int i = blockIdx.x * 256 + threadIdx.x;
    if (i < Nn * Dm) {
        int m = i / Dm, d = i % Dm;
        outT[(size_t)d * Nn + m] = tsw[i];
    }
}
__global__ void prep_adj(const float* __restrict__ adj, float* __restrict__ out)
{
    int i = blockIdx.x * 256 + threadIdx.x;
    if (i < NGc * Nn * Nn) {
        int s = i / (Nn * Nn);
        int r = i % (Nn * Nn);
        out[i] = adj[(size_t)r * NGc + s];
    }
}
__global__ void prep_ss(const float* __restrict__ gb, const float* __restrict__ bng,
                        const float* __restrict__ bnb, float* __restrict__ sc,
                        float* __restrict__ sh)
{
    int i = blockIdx.x * 256 + threadIdx.x;
    if (i < Ol * Dm) {
        sc[i] = bng[i];
        sh[i] = gb[i] * bng[i] + bnb[i];
    }
}

// ---------------------------------------------------------------------------
// Host-side composition
// ---------------------------------------------------------------------------
static void run_attention(const float* xq, const float* xkv,
                          const float* w, const float* bvec,
                          const float* res, float* buf, float* out)
{
    float* q  = buf + OFF_Q;
    float* k  = buf + OFF_K;
    float* v  = buf + OFF_V;
    float* kv = buf + OFF_KV;
    float* ks = buf + OFF_KSUM;
    float* at = buf + OFF_ATTN;
    // q = elu1(xq@W0+b0), k = elu1(xkv@W1+b1), v = xkv@W2+b2
    launch_gemm<2>(xq,  Dm, 0, 1, w,             Dm, 0, 1, q, Dm, 0,
                   bvec,        0, 1, nullptr, 0, 1, MT, Dm, Dm, 1);
    launch_gemm<2>(xkv, Dm, 0, 1, w + Dm * Dm,   Dm, 0, 1, k, Dm, 0,
                   bvec + Dm,   0, 1, nullptr, 0, 1, MT, Dm, Dm, 1);
    launch_gemm<1>(xkv, Dm, 0, 1, w + 2 * Dm * Dm, Dm, 0, 1, v, Dm, 0,
                   bvec + 2 * Dm, 0, 1, nullptr, 0, 1, MT, Dm, Dm, 1);
    kv_k<<<Bq * Hh, 256>>>(k, v, kv, ks);
    attn_o_k<<<dim3(Bq * Hh, (T + 63) / 64), 256>>>(q, kv, ks, at);
    // out = attn@W3 + b3 + res
    launch_gemm<4>(at, Dm, 0, 1, w + 3 * Dm * Dm, Dm, 0, 1, out, Dm, 0,
                   bvec + 3 * Dm, 0, 1, res, 0, 1, MT, Dm, Dm, 1);
}

extern "C" void kernel_launch(void* const* d_in, const int* in_sizes, int n_in,
                              void* d_out, int out_size)
{
    const float* x    = (const float*)d_in[0];
    const float* st   = (const float*)d_in[1];
    const float* adj  = (const float*)d_in[3];
    const float* eqw  = (const float*)d_in[4];
    const float* eqb  = (const float*)d_in[5];
    const float* ew1  = (const float*)d_in[6];
    const float* eb1  = (const float*)d_in[7];
    const float* ew2  = (const float*)d_in[8];
    const float* eb2  = (const float*)d_in[9];
    const float* elng = (const float*)d_in[10];
    const float* elnb = (const float*)d_in[11];
    const float* dsw  = (const float*)d_in[12];
    const float* dsb  = (const float*)d_in[13];
    const float* dcw  = (const float*)d_in[14];
    const float* dcb  = (const float*)d_in[15];
    const float* dw1  = (const float*)d_in[16];
    const float* db1  = (const float*)d_in[17];
    const float* dw2  = (const float*)d_in[18];
    const float* db2  = (const float*)d_in[19];
    const float* dlng = (const float*)d_in[20];
    const float* dlnb = (const float*)d_in[21];
    const float* ttw  = (const float*)d_in[22];
    const float* ttb  = (const float*)d_in[23];
    const float* tsw  = (const float*)d_in[24];
    const float* tsb  = (const float*)d_in[25];
    const float* gw   = (const float*)d_in[26];
    const float* gb   = (const float*)d_in[27];
    const float* bng  = (const float*)d_in[28];
    const float* bnb  = (const float*)d_in[29];

    float* buf = nullptr;
    cudaGetSymbolAddress((void**)&buf, g_buf);
    float* dout = (float*)d_out;

    const int BIG = 1 << 30;

    // ---- prep (independent of main chain)
    prep_tswT<<<(Nn * Dm + 255) / 256, 256>>>(tsw, buf + OFF_TSWT);
    prep_adj<<<(NGc * Nn * Nn + 255) / 256, 256>>>(adj, buf + OFF_ADJ);
    prep_ss<<<(Ol * Dm + 255) / 256, 256>>>(gb, bng, bnb, buf + OFF_SCALE, buf + OFF_SHIFT);

    // ---- encoder
    run_attention(x, x, eqw, eqb, x, buf, buf + OFF_H);
    ln_k<<<MT, 128>>>(buf + OFF_H, elng, elnb, buf + OFF_Y);
    launch_gemm<3>(buf + OFF_Y, Dm, 0, 1, ew1, Ff, 0, 1, buf + OFF_FFN, Ff, 0,
                   eb1, 0, 1, nullptr, 0, 1, MT, Ff, Dm, 1);
    launch_gemm<4>(buf + OFF_FFN, Ff, 0, 1, ew2, Dm, 0, 1, buf + OFF_H, Dm, 0,
                   eb2, 0, 1, buf + OFF_Y, 0, 1, MT, Dm, Ff, 1);
    ln_k<<<MT, 128>>>(buf + OFF_H, elng + Dm, elnb + Dm, buf + OFF_MEM);

    // ---- decoder self
    run_attention(st, st, dsw, dsb, st, buf, buf + OFF_H);
    ln_k<<<MT, 128>>>(buf + OFF_H, dlng, dlnb, buf + OFF_Y);
    // ---- decoder cross (q from stream, k/v from encoder memory)
    run_attention(buf + OFF_Y, buf + OFF_MEM, dcw, dcb, buf + OFF_Y, buf, buf + OFF_H);
    ln_k<<<MT, 128>>>(buf + OFF_H, dlng + Dm, dlnb + Dm, buf + OFF_Y);
    // ---- decoder ffn + final ln -> s_out
    launch_gemm<3>(buf + OFF_Y, Dm, 0, 1, dw1, Ff, 0, 1, buf + OFF_FFN, Ff, 0,
                   db1, 0, 1, nullptr, 0, 1, MT, Ff, Dm, 1);
    launch_gemm<4>(buf + OFF_FFN, Ff, 0, 1, dw2, Dm, 0, 1, buf + OFF_H, Dm, 0,
                   db2, 0, 1, buf + OFF_Y, 0, 1, MT, Dm, Ff, 1);
    ln_k<<<MT, 128>>>(buf + OFF_H, dlng + 2 * Dm, dlnb + 2 * Dm, buf + OFF_SOUT);
    if ((size_t)out_size >= 2 * MTD)
        cudaMemcpyAsync(dout + MTD, buf + OFF_SOUT, MTD * sizeof(float),
                        cudaMemcpyDeviceToDevice);

    // ---- xg (cat slice 0) from t_out
    tt_k<<<Bq * Nn, 256>>>(buf + OFF_MEM, ttw, ttb, buf + OFF_CAT);

    // ---- s_out2 = s_out @ ts_w^T + ts_b  -> (B*L, N, N)
    launch_gemm<1>(buf + OFF_SOUT, Dm, 0, 1, buf + OFF_TSWT, Nn, 0, 1,
                   buf + OFF_S2, Nn, 0, tsb, 0, 1, nullptr, 0, 1, MT, Nn, Dm, 1);

    // ---- static graph convs: per (b,o): X(512x207) @ A_s(207x207)
    const size_t catStride = (size_t)CC * Nn;
    const size_t sliceSz = (size_t)Dm * Nn;
    for (int s = 0; s < NGc; s++) {
        const float* As = buf + OFF_ADJ + (size_t)s * Nn * Nn;
        launch_gemm<0>(buf + OFF_CAT, Nn, catStride, BIG, As, Nn, 0, 1,
                       buf + OFF_CAT + (1 + 2 * s) * sliceSz, Nn, catStride,
                       nullptr, 0, 1, nullptr, 0, 1, Dm, Nn, Nn, Bq * Ol);
        launch_gemm<0>(buf + OFF_CAT + (1 + 2 * s) * sliceSz, Nn, catStride, BIG,
                       As, Nn, 0, 1,
                       buf + OFF_CAT + (2 + 2 * s) * sliceSz, Nn, catStride,
                       nullptr, 0, 1, nullptr, 0, 1, Dm, Nn, Nn, Bq * Ol);
    }
    // ---- adaptive graph convs: B matrix = s_out2[b,o] per batch
    launch_gemm<0>(buf + OFF_CAT, Nn, catStride, BIG,
                   buf + OFF_S2, Nn, (size_t)Nn * Nn, BIG,
                   buf + OFF_CAT + 7 * sliceSz, Nn, catStride,
                   nullptr, 0, 1, nullptr, 0, 1, Dm, Nn, Nn, Bq * Ol);
    launch_gemm<0>(buf + OFF_CAT + 7 * sliceSz, Nn, catStride, BIG,
                   buf + OFF_S2, Nn, (size_t)Nn * Nn, BIG,
                   buf + OFF_CAT + 8 * sliceSz, Nn, catStride,
                   nullptr, 0, 1, nullptr, 0, 1, Dm, Nn, Nn, Bq * Ol);

    // ---- GCN: g[d,n] = W_o(512x4608) @ cat(4608x207); bn affine; store dts[b,o,n,d]
    launch_gemm<5>(gw, CC, (size_t)Dm * CC, Ol,
                   buf + OFF_CAT, Nn, catStride, BIG,
                   dout, Dm, (size_t)Nn * Dm,
                   buf + OFF_SCALE, Dm, Ol,
                   buf + OFF_SHIFT, Dm, Ol,
                   Dm, Nn, CC, Bq * Ol);
}

// round 2
// speedup vs baseline: 2.1174x; 2.1174x over previous
#include <cuda_runtime.h>
#include <cuda_bf16.h>
#include <math.h>

// ---------------------------------------------------------------------------
// Problem constants
// ---------------------------------------------------------------------------
constexpr int Bq = 8, Lq = 12, Nn = 207, Dm = 512, Hh = 8, Ff = 2048;
constexpr int Ol = 12, NGc = 3;
constexpr int T  = Lq * Nn;          // 2484
constexpr int MT = Bq * T;           // 19872 rows
constexpr int E  = Dm / Hh;          // 64
constexpr int CC = Dm * (NGc + 1) * 2 + Dm;  // 4608

constexpr size_t MTD = (size_t)MT * Dm;        // 10,174,464
constexpr size_t OFF_Q    = 0;
constexpr size_t OFF_K    = 1 * MTD;
constexpr size_t OFF_V    = 2 * MTD;
constexpr size_t OFF_ATTN = 3 * MTD;
constexpr size_t OFF_H    = 4 * MTD;
constexpr size_t OFF_Y    = 5 * MTD;
constexpr size_t OFF_MEM  = 6 * MTD;
constexpr size_t OFF_SOUT = 7 * MTD;
constexpr size_t OFF_FFN  = 8 * MTD;                       // MT*Ff = 4*MTD
constexpr size_t OFF_KV   = 12 * MTD;                      // 64*4096
constexpr size_t OFF_KSUM = OFF_KV + (size_t)Bq * Hh * E * E;
constexpr size_t OFF_S2   = OFF_KSUM + (size_t)Bq * Hh * E;
constexpr size_t OFF_CAT  = OFF_S2 + (size_t)Bq * Lq * Nn * Nn;
constexpr size_t OFF_TSWT = OFF_CAT + (size_t)Bq * Ol * CC * Nn;
constexpr size_t OFF_ADJ  = OFF_TSWT + (size_t)Dm * Nn;
constexpr size_t OFF_SCALE= OFF_ADJ + (size_t)NGc * Nn * Nn;
constexpr size_t OFF_SHIFT= OFF_SCALE + (size_t)Ol * Dm;
constexpr size_t TOTAL    = OFF_SHIFT + (size_t)Ol * Dm;

__device__ __align__(16) float g_buf[TOTAL];

__device__ __forceinline__ unsigned f2tf(float x) {
    unsigned r;
    asm("cvt.rna.tf32.f32 %0, %1;" : "=r"(r) : "f"(x));
    return r;
}

// ---------------------------------------------------------------------------
// TF32 tensor-core batched GEMM: C = epi(A@B).
// A: MxK row-major (lda), B: KxN row-major (ldb).
// Block tile 128x128, BK=16, 8 warps (2 in m, 4 in n), warp tile 64x32,
// mma.sync.m16n8k8.tf32. Double-buffered smem, fully bounds-guarded.
// EPI: 0 none | 1 +bias[n] | 2 +bias[n],elu+1 | 3 +bias[n],gelu(tanh)
//      4 +bias[n]+res[m,n] | 5 val*P1[m]+P2[m], store C[n*ldc+m]
// ---------------------------------------------------------------------------
template <int EPI>
__global__ void __launch_bounds__(256)
gemm_k(const float* __restrict__ A, int lda, size_t sA, int mA,
       const float* __restrict__ Bm, int ldb, size_t sB, int mB,
       float* __restrict__ C, int ldc, size_t sC,
       const float* __restrict__ P1, size_t sP1, int mP1,
       const float* __restrict__ P2, size_t sP2, int mP2,
       int M, int N, int K)
{
    int bz = blockIdx.z;
    A  += (size_t)(bz % mA) * sA;
    Bm += (size_t)(bz % mB) * sB;
    C  += (size_t)bz * sC;
    const float* p1 = (EPI > 0) ? P1 + (size_t)(bz % mP1) * sP1 : nullptr;
    const float* p2 = (EPI == 4 || EPI == 5) ? P2 + (size_t)(bz % mP2) * sP2 : nullptr;

    __shared__ unsigned As[2][16][132];
    __shared__ unsigned Bs[2][16][132];

    int tid  = threadIdx.x;
    int lane = tid & 31, wid = tid >> 5;
    int wm = wid & 1, wn = wid >> 1;       // warps: 2 (m) x 4 (n)
    int g = lane >> 2, t = lane & 3;
    int m0 = blockIdx.y * 128;
    int n0 = blockIdx.x * 128;

    float acc[16][4];
#pragma unroll
    for (int i = 0; i < 16; i++)
#pragma unroll
        for (int j = 0; j < 4; j++) acc[i][j] = 0.f;

    const int a_m = tid >> 4;       // 0..15
    const int a_k = tid & 15;       // 0..15
    const int b_k = tid >> 7;       // 0..1
    const int b_n = tid & 127;      // 0..127

    float ra[8], rb[8];

    // prologue: tile 0
#pragma unroll
    for (int i = 0; i < 8; i++) {
        int gm = m0 + a_m + i * 16, gk = a_k;
        ra[i] = (gm < M && gk < K) ? A[(size_t)gm * lda + gk] : 0.f;
        int gk2 = b_k + i * 2, gn = n0 + b_n;
        rb[i] = (gk2 < K && gn < N) ? Bm[(size_t)gk2 * ldb + gn] : 0.f;
    }
#pragma unroll
    for (int i = 0; i < 8; i++) {
        As[0][a_k][a_m + i * 16] = f2tf(ra[i]);
        Bs[0][b_k + i * 2][b_n]  = f2tf(rb[i]);
    }
    __syncthreads();

    int nk = (K + 15) / 16;
    int cur = 0;
    for (int kb = 0; kb < nk; kb++) {
        if (kb + 1 < nk) {
            int k0 = (kb + 1) * 16;
#pragma unroll
            for (int i = 0; i < 8; i++) {
                int gm = m0 + a_m + i * 16, gk = k0 + a_k;
                ra[i] = (gm < M && gk < K) ? A[(size_t)gm * lda + gk] : 0.f;
                int gk2 = k0 + b_k + i * 2, gn = n0 + b_n;
                rb[i] = (gk2 < K && gn < N) ? Bm[(size_t)gk2 * ldb + gn] : 0.f;
            }
        }
#pragma unroll
        for (int ks = 0; ks < 2; ks++) {
            unsigned af[4][4], bf[4][2];
#pragma unroll
            for (int mt = 0; mt < 4; mt++) {
                int rm = wm * 64 + mt * 16 + g;
                af[mt][0] = As[cur][ks * 8 + t][rm];
                af[mt][1] = As[cur][ks * 8 + t][rm + 8];
                af[mt][2] = As[cur][ks * 8 + t + 4][rm];
                af[mt][3] = As[cur][ks * 8 + t + 4][rm + 8];
            }
#pragma unroll
            for (int nt = 0; nt < 4; nt++) {
                int cn = wn * 32 + nt * 8 + g;
                bf[nt][0] = Bs[cur][ks * 8 + t][cn];
                bf[nt][1] = Bs[cur][ks * 8 + t + 4][cn];
            }
#pragma unroll
            for (int mt = 0; mt < 4; mt++)
#pragma unroll
                for (int nt = 0; nt < 4; nt++) {
                    float* c = acc[mt * 4 + nt];
                    asm volatile(
                        "mma.sync.aligned.m16n8k8.row.col.f32.tf32.tf32.f32 "
                        "{%0,%1,%2,%3}, {%4,%5,%6,%7}, {%8,%9}, {%0,%1,%2,%3};"
                        : "+f"(c[0]), "+f"(c[1]), "+f"(c[2]), "+f"(c[3])
                        : "r"(af[mt][0]), "r"(af[mt][1]), "r"(af[mt][2]), "r"(af[mt][3]),
                          "r"(bf[nt][0]), "r"(bf[nt][1]));
                }
        }
        if (kb + 1 < nk) {
            int nxt = cur ^ 1;
#pragma unroll
            for (int i = 0; i < 8; i++) {
                As[nxt][a_k][a_m + i * 16] = f2tf(ra[i]);
                Bs[nxt][b_k + i * 2][b_n]  = f2tf(rb[i]);
            }
        }
        __syncthreads();
        cur ^= 1;
    }

    // epilogue
#pragma unroll
    for (int mt = 0; mt < 4; mt++)
#pragma unroll
        for (int nt = 0; nt < 4; nt++) {
            float* c = acc[mt * 4 + nt];
#pragma unroll
            for (int i = 0; i < 4; i++) {
                int m = m0 + wm * 64 + mt * 16 + g + (i >> 1) * 8;
                int n = n0 + wn * 32 + nt * 8 + 2 * t + (i & 1);
                if (m >= M || n >= N) continue;
                float v = c[i];
                if (EPI >= 1 && EPI <= 4) v += p1[n];
                if (EPI == 2) v = (v > 0.f) ? v + 1.f : expf(v);   // elu(x)+1
                if (EPI == 3) {
                    float cu = v * v * v;
                    v = 0.5f * v * (1.f + tanhf(0.7978845608028654f * (v + 0.044715f * cu)));
                }
                if (EPI == 4) v += p2[(size_t)m * ldc + n];
                if (EPI == 5) {
                    v = v * p1[m] + p2[m];
                    C[(size_t)n * ldc + m] = v;
                } else {
                    C[(size_t)m * ldc + n] = v;
                }
            }
        }
}

template <int EPI>
static void launch_gemm(const float* A, int lda, size_t sA, int mA,
                        const float* B, int ldb, size_t sB, int mB,
                        float* C, int ldc, size_t sC,
                        const float* P1, size_t sP1, int mP1,
                        const float* P2, size_t sP2, int mP2,
                        int M, int N, int K, int batch)
{
    dim3 grid((N + 127) / 128, (M + 127) / 128, batch);
    gemm_k<EPI><<<grid, 256>>>(A, lda, sA, mA, B, ldb, sB, mB, C, ldc, sC,
                               P1, sP1, mP1, P2, sP2, mP2, M, N, K);
}

// ---------------------------------------------------------------------------
// Linear attention internals
// kv[b,h,e,d] = sum_t kf[t,e]*v[t,d];  ksum[b,h,e] = sum_t kf[t,e]
// One block per (b,h); deterministic (no atomics).
// ---------------------------------------------------------------------------
__global__ void __launch_bounds__(256)
kv_k(const float* __restrict__ kf, const float* __restrict__ vv,
     float* __restrict__ kv, float* __restrict__ ksum)
{
    int bh = blockIdx.x;
    int b = bh >> 3, h = bh & 7;
    const float* kbase = kf + (size_t)b * T * Dm + h * E;
    const float* vbase = vv + (size_t)b * T * Dm + h * E;
    __shared__ float ks[16][64];
    __shared__ float vs[16][64];
    int tid = threadIdx.x;
    int tx = tid & 15, ty = tid >> 4;
    float acc[4][4] = {};
    float csum = 0.f;
    for (int t0 = 0; t0 < T; t0 += 16) {
#pragma unroll
        for (int i = 0; i < 4; i++) {
            int idx = tid + i * 256;
            int rr = idx >> 6, cc = idx & 63;
            int gt = t0 + rr;
            bool ok = gt < T;
            ks[rr][cc] = ok ? kbase[(size_t)gt * Dm + cc] : 0.f;
            vs[rr][cc] = ok ? vbase[(size_t)gt * Dm + cc] : 0.f;
        }
        __syncthreads();
#pragma unroll
        for (int r = 0; r < 16; r++) {
            float a[4], bb[4];
#pragma unroll
            for (int i = 0; i < 4; i++) a[i] = ks[r][tx * 4 + i];
#pragma unroll
            for (int j = 0; j < 4; j++) bb[j] = vs[r][ty * 4 + j];
#pragma unroll
            for (int i = 0; i < 4; i++)
#pragma unroll
                for (int j = 0; j < 4; j++)
                    acc[i][j] = fmaf(a[i], bb[j], acc[i][j]);
        }
        if (tid < 64) {
#pragma unroll
            for (int r = 0; r < 16; r++) csum += ks[r][tid];
        }
        __syncthreads();
    }
    float* kvb = kv + (size_t)bh * E * E;
#pragma unroll
    for (int i = 0; i < 4; i++)
#pragma unroll
        for (int j = 0; j < 4; j++)
            kvb[(tx * 4 + i) * E + ty * 4 + j] = acc[i][j];
    if (tid < 64) ksum[(size_t)bh * E + tid] = csum;
}

// o[b,t,h,d] = (sum_e qf[t,e]*kv[e,d]) / (sum_e qf[t,e]*ksum[e] + eps)
__global__ void __launch_bounds__(256)
attn_o_k(const float* __restrict__ qf, const float* __restrict__ kv,
         const float* __restrict__ ksum, float* __restrict__ out)
{
    int bh = blockIdx.x;
    int b = bh >> 3, h = bh & 7;
    int t0 = blockIdx.y * 64;
    const float* qbase = qf + (size_t)b * T * Dm + h * E;
    __shared__ float qs[64][64];
    __shared__ float kvs[64][65];
    __shared__ float kss[64];
    __shared__ float zs[64];
    int tid = threadIdx.x;
    int tx = tid & 15, ty = tid >> 4;
#pragma unroll
    for (int i = 0; i < 16; i++) {
        int idx = tid + i * 256;
        int r = idx >> 6, c = idx & 63;
        kvs[r][c] = kv[(size_t)bh * E * E + idx];
        int gt = t0 + r;
        qs[r][c] = (gt < T) ? qbase[(size_t)gt * Dm + c] : 0.f;
    }
    if (tid < 64) kss[tid] = ksum[(size_t)bh * E + tid];
    __syncthreads();
    if (tid < 64) {
        float s = 0.f;
#pragma unroll
        for (int e = 0; e < 64; e++) s = fmaf(qs[tid][e], kss[e], s);
        zs[tid] = 1.f / (s + 1e-6f);
    }
    __syncthreads();
    float acc[4][4] = {};
#pragma unroll
    for (int e = 0; e < 64; e++) {
        float a[4], bb[4];
#pragma unroll
        for (int i = 0; i < 4; i++) a[i] = qs[ty * 4 + i][e];
#pragma unroll
        for (int j = 0; j < 4; j++) bb[j] = kvs[e][tx * 4 + j];
#pragma unroll
        for (int i = 0; i < 4; i++)
#pragma unroll
            for (int j = 0; j < 4; j++)
                acc[i][j] = fmaf(a[i], bb[j], acc[i][j]);
    }
#pragma unroll
    for (int i = 0; i < 4; i++) {
        int t = t0 + ty * 4 + i;
        if (t >= T) continue;
        float z = zs[ty * 4 + i];
#pragma unroll
        for (int j = 0; j < 4; j++)
            out[((size_t)b * T + t) * Dm + h * E + tx * 4 + j] = acc[i][j] * z;
    }
}

// ---------------------------------------------------------------------------
// LayerNorm over D=512, one block per row (128 threads, float4)
// ---------------------------------------------------------------------------
__global__ void __launch_bounds__(128)
ln_k(const float* __restrict__ x, const float* __restrict__ g,
     const float* __restrict__ bvec, float* __restrict__ out)
{
    int r = blockIdx.x;
    int t = threadIdx.x;
    const float4* xr = (const float4*)(x + (size_t)r * Dm);
    float4 v = xr[t];
    float s = v.x + v.y + v.z + v.w;
    float q = v.x * v.x + v.y * v.y + v.z * v.z + v.w * v.w;
#pragma unroll
    for (int o = 16; o > 0; o >>= 1) {
        s += __shfl_down_sync(0xffffffffu, s, o);
        q += __shfl_down_sync(0xffffffffu, q, o);
    }
    __shared__ float ss[4], qq[4], mv[2];
    int w = t >> 5, l = t & 31;
    if (l == 0) { ss[w] = s; qq[w] = q; }
    __syncthreads();
    if (t == 0) {
        float S = ss[0] + ss[1] + ss[2] + ss[3];
        float Q = qq[0] + qq[1] + qq[2] + qq[3];
        float m = S * (1.f / 512.f);
        float var = Q * (1.f / 512.f) - m * m;
        mv[0] = m;
        mv[1] = rsqrtf(var + 1e-5f);
    }
    __syncthreads();
    float m = mv[0], inv = mv[1];
    float4 gg = ((const float4*)g)[t];
    float4 bb = ((const float4*)bvec)[t];
    float4 o4;
    o4.x = (v.x - m) * inv * gg.x + bb.x;
    o4.y = (v.y - m) * inv * gg.y + bb.y;
    o4.z = (v.z - m) * inv * gg.z + bb.z;
    o4.w = (v.w - m) * inv * gg.w + bb.w;
    ((float4*)(out + (size_t)r * Dm))[t] = o4;
}

// ---------------------------------------------------------------------------
// tt: xg[b,o,d,n] = sum_l tt_w[o,l]*t_out[b,l,n,d] + tt_b[o]  → cat slice 0
// one block per (b,n)
// ---------------------------------------------------------------------------
__global__ void __launch_bounds__(256)
tt_k(const float* __restrict__ tout, const float* __restrict__ ttw,
     const float* __restrict__ ttb, float* __restrict__ cat)
{
    int bn = blockIdx.x;
    int b = bn / Nn, n = bn % Nn;
    __shared__ float xs[12][512];
    __shared__ float w[144];
    int tid = threadIdx.x;
    if (tid < 144) w[tid] = ttw[tid];
    for (int l = 0; l < 12; l++)
        for (int d = tid; d < 512; d += 256)
            xs[l][d] = tout[(((size_t)b * Lq + l) * Nn + n) * Dm + d];
    __syncthreads();
    for (int od = tid; od < 12 * 512; od += 256) {
        int o = od >> 9, d = od & 511;
        float s = ttb[o];
#pragma unroll
        for (int l = 0; l < 12; l++) s = fmaf(w[o * 12 + l], xs[l][d], s);
        cat[(((size_t)b * Ol + o) * CC + d) * Nn + n] = s;
    }
}

// ---------------------------------------------------------------------------
// Small prep kernels
// ---------------------------------------------------------------------------
__global__ void prep_tswT(const float* __restrict__ tsw, float* __restrict__ outT)
{
    int i = blockIdx.x * 256 + threadIdx.x;
    if (i < Nn * Dm) {
        int m = i / Dm, d = i % Dm;
        outT[(size_t)d * Nn + m] = tsw[i];
    }
}
__global__ void prep_adj(const float* __restrict__ adj, float* __restrict__ out)
{
    int i = blockIdx.x * 256 + threadIdx.x;
    if (i < NGc * Nn * Nn) {
        int s = i / (Nn * Nn);
        int r = i % (Nn * Nn);
        out[i] = adj[(size_t)r * NGc + s];
    }
}
__global__ void prep_ss(const float* __restrict__ gb, const float* __restrict__ bng,
                        const float* __restrict__ bnb, float* __restrict__ sc,
                        float* __restrict__ sh)
{
    int i = blockIdx.x * 256 + threadIdx.x;
    if (i < Ol * Dm) {
        sc[i] = bng[i];
        sh[i] = gb[i] * bng[i] + bnb[i];
    }
}

// ---------------------------------------------------------------------------
// Host-side composition
// ---------------------------------------------------------------------------
static void run_attention(const float* xq, const float* xkv,
                          const float* w, const float* bvec,
                          const float* res, float* buf, float* out)
{
    float* q  = buf + OFF_Q;
    float* k  = buf + OFF_K;
    float* v  = buf + OFF_V;
    float* kv = buf + OFF_KV;
    float* ks = buf + OFF_KSUM;
    float* at = buf + OFF_ATTN;
    launch_gemm<2>(xq,  Dm, 0, 1, w,             Dm, 0, 1, q, Dm, 0,
                   bvec,        0, 1, nullptr, 0, 1, MT, Dm, Dm, 1);
    launch_gemm<2>(xkv, Dm, 0, 1, w + Dm * Dm,   Dm, 0, 1, k, Dm, 0,
                   bvec + Dm,   0, 1, nullptr, 0, 1, MT, Dm, Dm, 1);
    launch_gemm<1>(xkv, Dm, 0, 1, w + 2 * Dm * Dm, Dm, 0, 1, v, Dm, 0,
                   bvec + 2 * Dm, 0, 1, nullptr, 0, 1, MT, Dm, Dm, 1);
    kv_k<<<Bq * Hh, 256>>>(k, v, kv, ks);
    attn_o_k<<<dim3(Bq * Hh, (T + 63) / 64), 256>>>(q, kv, ks, at);
    launch_gemm<4>(at, Dm, 0, 1, w + 3 * Dm * Dm, Dm, 0, 1, out, Dm, 0,
                   bvec + 3 * Dm, 0, 1, res, 0, 1, MT, Dm, Dm, 1);
}

extern "C" void kernel_launch(void* const* d_in, const int* in_sizes, int n_in,
                              void* d_out, int out_size)
{
    const float* x    = (const float*)d_in[0];
    const float* st   = (const float*)d_in[1];
    const float* adj  = (const float*)d_in[3];
    const float* eqw  = (const float*)d_in[4];
    const float* eqb  = (const float*)d_in[5];
    const float* ew1  = (const float*)d_in[6];
    const float* eb1  = (const float*)d_in[7];
    const float* ew2  = (const float*)d_in[8];
    const float* eb2  = (const float*)d_in[9];
    const float* elng = (const float*)d_in[10];
    const float* elnb = (const float*)d_in[11];
    const float* dsw  = (const float*)d_in[12];
    const float* dsb  = (const float*)d_in[13];
    const float* dcw  = (const float*)d_in[14];
    const float* dcb  = (const float*)d_in[15];
    const float* dw1  = (const float*)d_in[16];
    const float* db1  = (const float*)d_in[17];
    const float* dw2  = (const float*)d_in[18];
    const float* db2  = (const float*)d_in[19];
    const float* dlng = (const float*)d_in[20];
    const float* dlnb = (const float*)d_in[21];
    const float* ttw  = (const float*)d_in[22];
    const float* ttb  = (const float*)d_in[23];
    const float* tsw  = (const float*)d_in[24];
    const float* tsb  = (const float*)d_in[25];
    const float* gw   = (const float*)d_in[26];
    const float* gb   = (const float*)d_in[27];
    const float* bng  = (const float*)d_in[28];
    const float* bnb  = (const float*)d_in[29];

    float* buf = nullptr;
    cudaGetSymbolAddress((void**)&buf, g_buf);
    float* dout = (float*)d_out;

    const int BIG = 1 << 30;

    // ---- prep (independent of main chain)
    prep_tswT<<<(Nn * Dm + 255) / 256, 256>>>(tsw, buf + OFF_TSWT);
    prep_adj<<<(NGc * Nn * Nn + 255) / 256, 256>>>(adj, buf + OFF_ADJ);
    prep_ss<<<(Ol * Dm + 255) / 256, 256>>>(gb, bng, bnb, buf + OFF_SCALE, buf + OFF_SHIFT);

    // ---- encoder
    run_attention(x, x, eqw, eqb, x, buf, buf + OFF_H);
    ln_k<<<MT, 128>>>(buf + OFF_H, elng, elnb, buf + OFF_Y);
    launch_gemm<3>(buf + OFF_Y, Dm, 0, 1, ew1, Ff, 0, 1, buf + OFF_FFN, Ff, 0,
                   eb1, 0, 1, nullptr, 0, 1, MT, Ff, Dm, 1);
    launch_gemm<4>(buf + OFF_FFN, Ff, 0, 1, ew2, Dm, 0, 1, buf + OFF_H, Dm, 0,
                   eb2, 0, 1, buf + OFF_Y, 0, 1, MT, Dm, Ff, 1);
    ln_k<<<MT, 128>>>(buf + OFF_H, elng + Dm, elnb + Dm, buf + OFF_MEM);

    // ---- decoder self
    run_attention(st, st, dsw, dsb, st, buf, buf + OFF_H);
    ln_k<<<MT, 128>>>(buf + OFF_H, dlng, dlnb, buf + OFF_Y);
    // ---- decoder cross (q from stream, k/v from encoder memory)
    run_attention(buf + OFF_Y, buf + OFF_MEM, dcw, dcb, buf + OFF_Y, buf, buf + OFF_H);
    ln_k<<<MT, 128>>>(buf + OFF_H, dlng + Dm, dlnb + Dm, buf + OFF_Y);
    // ---- decoder ffn + final ln -> s_out
    launch_gemm<3>(buf + OFF_Y, Dm, 0, 1, dw1, Ff, 0, 1, buf + OFF_FFN, Ff, 0,
                   db1, 0, 1, nullptr, 0, 1, MT, Ff, Dm, 1);
    launch_gemm<4>(buf + OFF_FFN, Ff, 0, 1, dw2, Dm, 0, 1, buf + OFF_H, Dm, 0,
                   db2, 0, 1, buf + OFF_Y, 0, 1, MT, Dm, Ff, 1);
    ln_k<<<MT, 128>>>(buf + OFF_H, dlng + 2 * Dm, dlnb + 2 * Dm, buf + OFF_SOUT);
    if ((size_t)out_size >= 2 * MTD)
        cudaMemcpyAsync(dout + MTD, buf + OFF_SOUT, MTD * sizeof(float),
                        cudaMemcpyDeviceToDevice);

    // ---- xg (cat slice 0) from t_out
    tt_k<<<Bq * Nn, 256>>>(buf + OFF_MEM, ttw, ttb, buf + OFF_CAT);

    // ---- s_out2 = s_out @ ts_w^T + ts_b  -> (B*L, N, N)
    launch_gemm<1>(buf + OFF_SOUT, Dm, 0, 1, buf + OFF_TSWT, Nn, 0, 1,
                   buf + OFF_S2, Nn, 0, tsb, 0, 1, nullptr, 0, 1, MT, Nn, Dm, 1);

    // ---- static graph convs: per (b,o): X(512x207) @ A_s(207x207)
    const size_t catStride = (size_t)CC * Nn;
    const size_t sliceSz = (size_t)Dm * Nn;
    for (int s = 0; s < NGc; s++) {
        const float* As = buf + OFF_ADJ + (size_t)s * Nn * Nn;
        launch_gemm<0>(buf + OFF_CAT, Nn, catStride, BIG, As, Nn, 0, 1,
                       buf + OFF_CAT + (1 + 2 * s) * sliceSz, Nn, catStride,
                       nullptr, 0, 1, nullptr, 0, 1, Dm, Nn, Nn, Bq * Ol);
        launch_gemm<0>(buf + OFF_CAT + (1 + 2 * s) * sliceSz, Nn, catStride, BIG,
                       As, Nn, 0, 1,
                       buf + OFF_CAT + (2 + 2 * s) * sliceSz, Nn, catStride,
                       nullptr, 0, 1, nullptr, 0, 1, Dm, Nn, Nn, Bq * Ol);
    }
    // ---- adaptive graph convs: B matrix = s_out2[b,o] per batch
    launch_gemm<0>(buf + OFF_CAT, Nn, catStride, BIG,
                   buf + OFF_S2, Nn, (size_t)Nn * Nn, BIG,
                   buf + OFF_CAT + 7 * sliceSz, Nn, catStride,
                   nullptr, 0, 1, nullptr, 0, 1, Dm, Nn, Nn, Bq * Ol);
    launch_gemm<0>(buf + OFF_CAT + 7 * sliceSz, Nn, catStride, BIG,
                   buf + OFF_S2, Nn, (size_t)Nn * Nn, BIG,
                   buf + OFF_CAT + 8 * sliceSz, Nn, catStride,
                   nullptr, 0, 1, nullptr, 0, 1, Dm, Nn, Nn, Bq * Ol);

    // ---- GCN: g[d,n] = W_o(512x4608) @ cat(4608x207); bn affine; store dts[b,o,n,d]
    launch_gemm<5>(gw, CC, (size_t)Dm * CC, Ol,
                   buf + OFF_CAT, Nn, catStride, BIG,
                   dout, Dm, (size_t)Nn * Dm,
                   buf + OFF_SCALE, Dm, Ol,
                   buf + OFF_SHIFT, Dm, Ol,
                   Dm, Nn, CC, Bq * Ol);
}

// round 3
// speedup vs baseline: 2.1217x; 1.0020x over previous
#include <cuda_runtime.h>
#include <cuda_bf16.h>
#include <math.h>

// ---------------------------------------------------------------------------
// Problem constants
// ---------------------------------------------------------------------------
constexpr int Bq = 8, Lq = 12, Nn = 207, Dm = 512, Hh = 8, Ff = 2048;
constexpr int Ol = 12, NGc = 3;
constexpr int T  = Lq * Nn;          // 2484
constexpr int MT = Bq * T;           // 19872 rows
constexpr int E  = Dm / Hh;          // 64
constexpr int CC = Dm * (NGc + 1) * 2 + Dm;  // 4608
constexpr int KVS = 4;               // kv split factor
constexpr int TCH = T / KVS;         // 621

constexpr size_t MTD = (size_t)MT * Dm;        // 10,174,464
constexpr size_t OFF_Q    = 0;
constexpr size_t OFF_K    = 1 * MTD;
constexpr size_t OFF_V    = 2 * MTD;
constexpr size_t OFF_ATTN = 3 * MTD;
constexpr size_t OFF_H    = 4 * MTD;
constexpr size_t OFF_Y    = 5 * MTD;
constexpr size_t OFF_MEM  = 6 * MTD;
constexpr size_t OFF_SOUT = 7 * MTD;
constexpr size_t OFF_FFN  = 8 * MTD;                       // MT*Ff = 4*MTD
constexpr size_t OFF_KV   = 12 * MTD;
constexpr size_t OFF_KSUM = OFF_KV + (size_t)Bq * Hh * E * E;
constexpr size_t OFF_S2   = OFF_KSUM + (size_t)Bq * Hh * E;
constexpr size_t OFF_CAT  = OFF_S2 + (size_t)Bq * Lq * Nn * Nn;
constexpr size_t OFF_TSWT = OFF_CAT + (size_t)Bq * Ol * CC * Nn;
constexpr size_t OFF_ADJ  = OFF_TSWT + (size_t)Dm * Nn;
constexpr size_t OFF_SCALE= OFF_ADJ + (size_t)NGc * Nn * Nn;
constexpr size_t OFF_SHIFT= OFF_SCALE + (size_t)Ol * Dm;
constexpr size_t OFF_KVP  = OFF_SHIFT + (size_t)Ol * Dm;       // KVS*64*E*E
constexpr size_t OFF_KSP  = OFF_KVP + (size_t)KVS * 64 * E * E;
constexpr size_t TOTAL    = OFF_KSP + (size_t)KVS * 64 * E;

__device__ __align__(16) float g_buf[TOTAL];

__device__ __forceinline__ unsigned f2tf(float x) {
    unsigned r;
    asm("cvt.rna.tf32.f32 %0, %1;" : "=r"(r) : "f"(x));
    return r;
}
__device__ __forceinline__ int swz(int r) {
    return (((r & 7) ^ ((r >> 3) & 7)) << 1);
}

// ---------------------------------------------------------------------------
// TF32 tensor-core batched GEMM: C = epi(A@B).
// Block 128x128, BK=16, 8 warps (2m x 4n), warp tile 64x32, m16n8k8.tf32.
// Permuted-k + swizzled smem -> LDS.64 fragment loads; incremental pointers.
// EPI: 0 none | 1 +bias[n] | 2 +bias[n],elu+1 | 3 +bias[n],gelu(tanh)
//      4 +bias[n]+res[m,n] | 5 val*P1[m]+P2[m], store C[n*ldc+m]
// ---------------------------------------------------------------------------
template <int EPI>
__global__ void __launch_bounds__(256, 2)
gemm_k(const float* __restrict__ A, int lda, size_t sA, int mA,
       const float* __restrict__ Bm, int ldb, size_t sB, int mB,
       float* __restrict__ C, int ldc, size_t sC,
       const float* __restrict__ P1, size_t sP1, int mP1,
       const float* __restrict__ P2, size_t sP2, int mP2,
       int M, int N, int K)
{
    int bz = blockIdx.z;
    A  += (size_t)(bz % mA) * sA;
    Bm += (size_t)(bz % mB) * sB;
    C  += (size_t)bz * sC;
    const float* p1 = (EPI > 0) ? P1 + (size_t)(bz % mP1) * sP1 : nullptr;
    const float* p2 = (EPI == 4 || EPI == 5) ? P2 + (size_t)(bz % mP2) * sP2 : nullptr;

    __shared__ unsigned As[2][128][16];
    __shared__ unsigned Bs[2][128][16];

    int tid  = threadIdx.x;
    int lane = tid & 31, wid = tid >> 5;
    int wm = wid & 1, wn = wid >> 1;
    int g = lane >> 2, t = lane & 3;
    int m0 = blockIdx.y * 128;
    int n0 = blockIdx.x * 128;

    float acc[16][4];
#pragma unroll
    for (int i = 0; i < 16; i++)
#pragma unroll
        for (int j = 0; j < 4; j++) acc[i][j] = 0.f;

    // ---- loader setup
    const int a_m = tid >> 4, a_k = tid & 15;       // A: 16 m x 16 k per pass
    const int b_k = tid >> 7, b_n = tid & 127;      // B: 2 k x 128 n per pass
    const int akp = (a_k & 8) | ((a_k & 3) << 1) | ((a_k >> 2) & 1);

    int aidx[8], bidx[8];
    bool am[8];
#pragma unroll
    for (int i = 0; i < 8; i++) {
        int ml = a_m + 16 * i;
        aidx[i] = ml * 16 + (akp ^ swz(ml));
        am[i] = (m0 + ml) < M;
        int kk = b_k + 2 * i;
        int bkp = (kk & 8) | ((kk & 3) << 1) | ((kk >> 2) & 1);
        bidx[i] = b_n * 16 + (bkp ^ swz(b_n));
    }
    const bool bnok = (n0 + b_n) < N;

    const float* aP = A + (size_t)(m0 + a_m) * lda + a_k;
    const float* bP = Bm + (size_t)b_k * ldb + (n0 + b_n);
    const size_t aStep = (size_t)16 * lda;
    const size_t bStep = (size_t)2 * ldb;
    const size_t bAdv  = (size_t)16 * ldb;

    float va[8], vb[8];

    auto LOAD = [&](int kbase) {
        bool ka = (kbase + a_k) < K;
#pragma unroll
        for (int i = 0; i < 8; i++) {
            va[i] = (am[i] && ka) ? aP[i * aStep] : 0.f;
            bool kb_ok = (kbase + b_k + 2 * i) < K;
            vb[i] = (bnok && kb_ok) ? bP[i * bStep] : 0.f;
        }
        aP += 16;
        bP += bAdv;
    };
    auto STORE = [&](int buf) {
        unsigned* as = &As[buf][0][0];
        unsigned* bs = &Bs[buf][0][0];
#pragma unroll
        for (int i = 0; i < 8; i++) {
            as[aidx[i]] = f2tf(va[i]);
            bs[bidx[i]] = f2tf(vb[i]);
        }
    };
    auto COMPUTE = [&](int buf) {
        const unsigned* as = &As[buf][0][0];
        const unsigned* bs = &Bs[buf][0][0];
#pragma unroll
        for (int ks = 0; ks < 2; ks++) {
            int kp = (ks << 3) | (t << 1);
            unsigned af[4][4], bf[4][2];
#pragma unroll
            for (int mt = 0; mt < 4; mt++) {
                int rm = wm * 64 + mt * 16 + g;
                uint2 lo = *(const uint2*)(as + rm * 16 + (kp ^ swz(rm)));
                int rm2 = rm + 8;
                uint2 hi = *(const uint2*)(as + rm2 * 16 + (kp ^ swz(rm2)));
                af[mt][0] = lo.x; af[mt][1] = hi.x;
                af[mt][2] = lo.y; af[mt][3] = hi.y;
            }
#pragma unroll
            for (int nt = 0; nt < 4; nt++) {
                int cn = wn * 32 + nt * 8 + g;
                uint2 bb = *(const uint2*)(bs + cn * 16 + (kp ^ swz(cn)));
                bf[nt][0] = bb.x; bf[nt][1] = bb.y;
            }
#pragma unroll
            for (int mt = 0; mt < 4; mt++)
#pragma unroll
                for (int nt = 0; nt < 4; nt++) {
                    float* c = acc[mt * 4 + nt];
                    asm volatile(
                        "mma.sync.aligned.m16n8k8.row.col.f32.tf32.tf32.f32 "
                        "{%0,%1,%2,%3}, {%4,%5,%6,%7}, {%8,%9}, {%0,%1,%2,%3};"
                        : "+f"(c[0]), "+f"(c[1]), "+f"(c[2]), "+f"(c[3])
                        : "r"(af[mt][0]), "r"(af[mt][1]), "r"(af[mt][2]), "r"(af[mt][3]),
                          "r"(bf[nt][0]), "r"(bf[nt][1]));
                }
        }
    };

    int nk = (K + 15) >> 4;
    LOAD(0);
    STORE(0);
    __syncthreads();
    int cur = 0;
    for (int kb = 0; kb < nk; kb++) {
        if (kb + 1 < nk) LOAD((kb + 1) << 4);
        COMPUTE(cur);
        if (kb + 1 < nk) STORE(cur ^ 1);
        __syncthreads();
        cur ^= 1;
    }

    // epilogue
#pragma unroll
    for (int mt = 0; mt < 4; mt++)
#pragma unroll
        for (int nt = 0; nt < 4; nt++) {
            float* c = acc[mt * 4 + nt];
#pragma unroll
            for (int i = 0; i < 4; i++) {
                int m = m0 + wm * 64 + mt * 16 + g + (i >> 1) * 8;
                int n = n0 + wn * 32 + nt * 8 + 2 * t + (i & 1);
                if (m >= M || n >= N) continue;
                float v = c[i];
                if (EPI >= 1 && EPI <= 4) v += p1[n];
                if (EPI == 2) v = (v > 0.f) ? v + 1.f : expf(v);   // elu(x)+1
                if (EPI == 3) {
                    float cu = v * v * v;
                    v = 0.5f * v * (1.f + tanhf(0.7978845608028654f * (v + 0.044715f * cu)));
                }
                if (EPI == 4) v += p2[(size_t)m * ldc + n];
                if (EPI == 5) {
                    v = v * p1[m] + p2[m];
                    C[(size_t)n * ldc + m] = v;
                } else {
                    C[(size_t)m * ldc + n] = v;
                }
            }
        }
}

template <int EPI>
static void launch_gemm(const float* A, int lda, size_t sA, int mA,
                        const float* B, int ldb, size_t sB, int mB,
                        float* C, int ldc, size_t sC,
                        const float* P1, size_t sP1, int mP1,
                        const float* P2, size_t sP2, int mP2,
                        int M, int N, int K, int batch)
{
    dim3 grid((N + 127) / 128, (M + 127) / 128, batch);
    gemm_k<EPI><<<grid, 256>>>(A, lda, sA, mA, B, ldb, sB, mB, C, ldc, sC,
                               P1, sP1, mP1, P2, sP2, mP2, M, N, K);
}

// ---------------------------------------------------------------------------
// Linear attention internals.
// Split kv over T into KVS deterministic chunks + reduce (no atomics).
// ---------------------------------------------------------------------------
__global__ void __launch_bounds__(256)
kv_part_k(const float* __restrict__ kf, const float* __restrict__ vv,
          float* __restrict__ kvp, float* __restrict__ ksp)
{
    int bh = blockIdx.x;
    int sp = blockIdx.y;
    int b = bh >> 3, h = bh & 7;
    int ts = sp * TCH, te = ts + TCH;
    const float* kbase = kf + (size_t)b * T * Dm + h * E;
    const float* vbase = vv + (size_t)b * T * Dm + h * E;
    __shared__ float ks[16][64];
    __shared__ float vs[16][64];
    int tid = threadIdx.x;
    int tx = tid & 15, ty = tid >> 4;
    float acc[4][4] = {};
    float csum = 0.f;
    for (int t0 = ts; t0 < te; t0 += 16) {
#pragma unroll
        for (int i = 0; i < 4; i++) {
            int idx = tid + i * 256;
            int rr = idx >> 6, cc = idx & 63;
            int gt = t0 + rr;
            bool ok = gt < te;
            ks[rr][cc] = ok ? kbase[(size_t)gt * Dm + cc] : 0.f;
            vs[rr][cc] = ok ? vbase[(size_t)gt * Dm + cc] : 0.f;
        }
        __syncthreads();
#pragma unroll
        for (int r = 0; r < 16; r++) {
            float a[4], bb[4];
#pragma unroll
            for (int i = 0; i < 4; i++) a[i] = ks[r][tx * 4 + i];
#pragma unroll
            for (int j = 0; j < 4; j++) bb[j] = vs[r][ty * 4 + j];
#pragma unroll
            for (int i = 0; i < 4; i++)
#pragma unroll
                for (int j = 0; j < 4; j++)
                    acc[i][j] = fmaf(a[i], bb[j], acc[i][j]);
        }
        if (tid < 64) {
#pragma unroll
            for (int r = 0; r < 16; r++) csum += ks[r][tid];
        }
        __syncthreads();
    }
    float* kvb = kvp + ((size_t)sp * 64 + bh) * E * E;
#pragma unroll
    for (int i = 0; i < 4; i++)
#pragma unroll
        for (int j = 0; j < 4; j++)
            kvb[(tx * 4 + i) * E + ty * 4 + j] = acc[i][j];
    if (tid < 64) ksp[((size_t)sp * 64 + bh) * E + tid] = csum;
}

__global__ void __launch_bounds__(256)
kv_reduce_k(const float* __restrict__ kvp, const float* __restrict__ ksp,
            float* __restrict__ kv, float* __restrict__ ksum)
{
    const int NKV = 64 * E * E;
    int i = blockIdx.x * 256 + threadIdx.x;
    if (i < NKV) {
        float s = 0.f;
#pragma unroll
        for (int sp = 0; sp < KVS; sp++) s += kvp[(size_t)sp * NKV + i];
        kv[i] = s;
    } else if (i < NKV + 64 * E) {
        int j = i - NKV;
        float s = 0.f;
#pragma unroll
        for (int sp = 0; sp < KVS; sp++) s += ksp[(size_t)sp * 64 * E + j];
        ksum[j] = s;
    }
}

// o[b,t,h,d] = (sum_e qf[t,e]*kv[e,d]) / (sum_e qf[t,e]*ksum[e] + eps)
__global__ void __launch_bounds__(256)
attn_o_k(const float* __restrict__ qf, const float* __restrict__ kv,
         const float* __restrict__ ksum, float* __restrict__ out)
{
    int bh = blockIdx.x;
    int b = bh >> 3, h = bh & 7;
    int t0 = blockIdx.y * 64;
    const float* qbase = qf + (size_t)b * T * Dm + h * E;
    __shared__ float qs[64][64];
    __shared__ float kvs[64][65];
    __shared__ float kss[64];
    __shared__ float zs[64];
    int tid = threadIdx.x;
    int tx = tid & 15, ty = tid >> 4;
#pragma unroll
    for (int i = 0; i < 16; i++) {
        int idx = tid + i * 256;
        int r = idx >> 6, c = idx & 63;
        kvs[r][c] = kv[(size_t)bh * E * E + idx];
        int gt = t0 + r;
        qs[r][c] = (gt < T) ? qbase[(size_t)gt * Dm + c] : 0.f;
    }
    if (tid < 64) kss[tid] = ksum[(size_t)bh * E + tid];
    __syncthreads();
    if (tid < 64) {
        float s = 0.f;
#pragma unroll
        for (int e = 0; e < 64; e++) s = fmaf(qs[tid][e], kss[e], s);
        zs[tid] = 1.f / (s + 1e-6f);
    }
    __syncthreads();
    float acc[4][4] = {};
#pragma unroll
    for (int e = 0; e < 64; e++) {
        float a[4], bb[4];
#pragma unroll
        for (int i = 0; i < 4; i++) a[i] = qs[ty * 4 + i][e];
#pragma unroll
        for (int j = 0; j < 4; j++) bb[j] = kvs[e][tx * 4 + j];
#pragma unroll
        for (int i = 0; i < 4; i++)
#pragma unroll
            for (int j = 0; j < 4; j++)
                acc[i][j] = fmaf(a[i], bb[j], acc[i][j]);
    }
#pragma unroll
    for (int i = 0; i < 4; i++) {
        int t = t0 + ty * 4 + i;
        if (t >= T) continue;
        float z = zs[ty * 4 + i];
#pragma unroll
        for (int j = 0; j < 4; j++)
            out[((size_t)b * T + t) * Dm + h * E + tx * 4 + j] = acc[i][j] * z;
    }
}

// ---------------------------------------------------------------------------
// LayerNorm over D=512, one block per row
// ---------------------------------------------------------------------------
__global__ void __launch_bounds__(128)
ln_k(const float* __restrict__ x, const float* __restrict__ g,
     const float* __restrict__ bvec, float* __restrict__ out)
{
    int r = blockIdx.x;
    int t = threadIdx.x;
    const float4* xr = (const float4*)(x + (size_t)r * Dm);
    float4 v = xr[t];
    float s = v.x + v.y + v.z + v.w;
    float q = v.x * v.x + v.y * v.y + v.z * v.z + v.w * v.w;
#pragma unroll
    for (int o = 16; o > 0; o >>= 1) {
        s += __shfl_down_sync(0xffffffffu, s, o);
        q += __shfl_down_sync(0xffffffffu, q, o);
    }
    __shared__ float ss[4], qq[4], mv[2];
    int w = t >> 5, l = t & 31;
    if (l == 0) { ss[w] = s; qq[w] = q; }
    __syncthreads();
    if (t == 0) {
        float S = ss[0] + ss[1] + ss[2] + ss[3];
        float Q = qq[0] + qq[1] + qq[2] + qq[3];
        float m = S * (1.f / 512.f);
        float var = Q * (1.f / 512.f) - m * m;
        mv[0] = m;
        mv[1] = rsqrtf(var + 1e-5f);
    }
    __syncthreads();
    float m = mv[0], inv = mv[1];
    float4 gg = ((const float4*)g)[t];
    float4 bb = ((const float4*)bvec)[t];
    float4 o4;
    o4.x = (v.x - m) * inv * gg.x + bb.x;
    o4.y = (v.y - m) * inv * gg.y + bb.y;
    o4.z = (v.z - m) * inv * gg.z + bb.z;
    o4.w = (v.w - m) * inv * gg.w + bb.w;
    ((float4*)(out + (size_t)r * Dm))[t] = o4;
}

// ---------------------------------------------------------------------------
// tt: xg[b,o,d,n] = sum_l tt_w[o,l]*t_out[b,l,n,d] + tt_b[o] -> cat slice 0
// ---------------------------------------------------------------------------
__global__ void __launch_bounds__(256)
tt_k(const float* __restrict__ tout, const float* __restrict__ ttw,
     const float* __restrict__ ttb, float* __restrict__ cat)
{
    int bn = blockIdx.x;
    int b = bn / Nn, n = bn % Nn;
    __shared__ float xs[12][512];
    __shared__ float w[144];
    int tid = threadIdx.x;
    if (tid < 144) w[tid] = ttw[tid];
    for (int l = 0; l < 12; l++)
        for (int d = tid; d < 512; d += 256)
            xs[l][d] = tout[(((size_t)b * Lq + l) * Nn + n) * Dm + d];
    __syncthreads();
    for (int od = tid; od < 12 * 512; od += 256) {
        int o = od >> 9, d = od & 511;
        float s = ttb[o];
#pragma unroll
        for (int l = 0; l < 12; l++) s = fmaf(w[o * 12 + l], xs[l][d], s);
        cat[(((size_t)b * Ol + o) * CC + d) * Nn + n] = s;
    }
}

// ---------------------------------------------------------------------------
// Small prep kernels
// ---------------------------------------------------------------------------
__global__ void prep_tswT(const float* __restrict__ tsw, float* __restrict__ outT)
{
    int i = blockIdx.x * 256 + threadIdx.x;
    if (i < Nn * Dm) {
        int m = i / Dm, d = i % Dm;
        outT[(size_t)d * Nn + m] = tsw[i];
    }
}
__global__ void prep_adj(const float* __restrict__ adj, float* __restrict__ out)
{
    int i = blockIdx.x * 256 + threadIdx.x;
    if (i < NGc * Nn * Nn) {
        int s = i / (Nn * Nn);
        int r = i % (Nn * Nn);
        out[i] = adj[(size_t)r * NGc + s];
    }
}
__global__ void prep_ss(const float* __restrict__ gb, const float* __restrict__ bng,
                        const float* __restrict__ bnb, float* __restrict__ sc,
                        float* __restrict__ sh)
{
    int i = blockIdx.x * 256 + threadIdx.x;
    if (i < Ol * Dm) {
        sc[i] = bng[i];
        sh[i] = gb[i] * bng[i] + bnb[i];
    }
}

// ---------------------------------------------------------------------------
// Host-side composition
// ---------------------------------------------------------------------------
static void run_attention(const float* xq, const float* xkv,
                          const float* w, const float* bvec,
                          const float* res, float* buf, float* out)
{
    float* q  = buf + OFF_Q;
    float* k  = buf + OFF_K;
    float* v  = buf + OFF_V;
    float* kv = buf + OFF_KV;
    float* ks = buf + OFF_KSUM;
    float* at = buf + OFF_ATTN;
    launch_gemm<2>(xq,  Dm, 0, 1, w,             Dm, 0, 1, q, Dm, 0,
                   bvec,        0, 1, nullptr, 0, 1, MT, Dm, Dm, 1);
    launch_gemm<2>(xkv, Dm, 0, 1, w + Dm * Dm,   Dm, 0, 1, k, Dm, 0,
                   bvec + Dm,   0, 1, nullptr, 0, 1, MT, Dm, Dm, 1);
    launch_gemm<1>(xkv, Dm, 0, 1, w + 2 * Dm * Dm, Dm, 0, 1, v, Dm, 0,
                   bvec + 2 * Dm, 0, 1, nullptr, 0, 1, MT, Dm, Dm, 1);
    kv_part_k<<<dim3(Bq * Hh, KVS), 256>>>(k, v, buf + OFF_KVP, buf + OFF_KSP);
    kv_reduce_k<<<(64 * E * E + 64 * E + 255) / 256, 256>>>(buf + OFF_KVP, buf + OFF_KSP, kv, ks);
    attn_o_k<<<dim3(Bq * Hh, (T + 63) / 64), 256>>>(q, kv, ks, at);
    launch_gemm<4>(at, Dm, 0, 1, w + 3 * Dm * Dm, Dm, 0, 1, out, Dm, 0,
                   bvec + 3 * Dm, 0, 1, res, 0, 1, MT, Dm, Dm, 1);
}

extern "C" void kernel_launch(void* const* d_in, const int* in_sizes, int n_in,
                              void* d_out, int out_size)
{
    const float* x    = (const float*)d_in[0];
    const float* st   = (const float*)d_in[1];
    const float* adj  = (const float*)d_in[3];
    const float* eqw  = (const float*)d_in[4];
    const float* eqb  = (const float*)d_in[5];
    const float* ew1  = (const float*)d_in[6];
    const float* eb1  = (const float*)d_in[7];
    const float* ew2  = (const float*)d_in[8];
    const float* eb2  = (const float*)d_in[9];
    const float* elng = (const float*)d_in[10];
    const float* elnb = (const float*)d_in[11];
    const float* dsw  = (const float*)d_in[12];
    const float* dsb  = (const float*)d_in[13];
    const float* dcw  = (const float*)d_in[14];
    const float* dcb  = (const float*)d_in[15];
    const float* dw1  = (const float*)d_in[16];
    const float* db1  = (const float*)d_in[17];
    const float* dw2  = (const float*)d_in[18];
    const float* db2  = (const float*)d_in[19];
    const float* dlng = (const float*)d_in[20];
    const float* dlnb = (const float*)d_in[21];
    const float* ttw  = (const float*)d_in[22];
    const float* ttb  = (const float*)d_in[23];
    const float* tsw  = (const float*)d_in[24];
    const float* tsb  = (const float*)d_in[25];
    const float* gw   = (const float*)d_in[26];
    const float* gb   = (const float*)d_in[27];
    const float* bng  = (const float*)d_in[28];
    const float* bnb  = (const float*)d_in[29];

    float* buf = nullptr;
    cudaGetSymbolAddress((void**)&buf, g_buf);
    float* dout = (float*)d_out;

    const int BIG = 1 << 30;

    // ---- prep (independent of main chain)
    prep_tswT<<<(Nn * Dm + 255) / 256, 256>>>(tsw, buf + OFF_TSWT);
    prep_adj<<<(NGc * Nn * Nn + 255) / 256, 256>>>(adj, buf + OFF_ADJ);
    prep_ss<<<(Ol * Dm + 255) / 256, 256>>>(gb, bng, bnb, buf + OFF_SCALE, buf + OFF_SHIFT);

    // ---- encoder
    run_attention(x, x, eqw, eqb, x, buf, buf + OFF_H);
    ln_k<<<MT, 128>>>(buf + OFF_H, elng, elnb, buf + OFF_Y);
    launch_gemm<3>(buf + OFF_Y, Dm, 0, 1, ew1, Ff, 0, 1, buf + OFF_FFN, Ff, 0,
                   eb1, 0, 1, nullptr, 0, 1, MT, Ff, Dm, 1);
    launch_gemm<4>(buf + OFF_FFN, Ff, 0, 1, ew2, Dm, 0, 1, buf + OFF_H, Dm, 0,
                   eb2, 0, 1, buf + OFF_Y, 0, 1, MT, Dm, Ff, 1);
    ln_k<<<MT, 128>>>(buf + OFF_H, elng + Dm, elnb + Dm, buf + OFF_MEM);

    // ---- decoder self
    run_attention(st, st, dsw, dsb, st, buf, buf + OFF_H);
    ln_k<<<MT, 128>>>(buf + OFF_H, dlng, dlnb, buf + OFF_Y);
    // ---- decoder cross
    run_attention(buf + OFF_Y, buf + OFF_MEM, dcw, dcb, buf + OFF_Y, buf, buf + OFF_H);
    ln_k<<<MT, 128>>>(buf + OFF_H, dlng + Dm, dlnb + Dm, buf + OFF_Y);
    // ---- decoder ffn + final ln -> s_out
    launch_gemm<3>(buf + OFF_Y, Dm, 0, 1, dw1, Ff, 0, 1, buf + OFF_FFN, Ff, 0,
                   db1, 0, 1, nullptr, 0, 1, MT, Ff, Dm, 1);
    launch_gemm<4>(buf + OFF_FFN, Ff, 0, 1, dw2, Dm, 0, 1, buf + OFF_H, Dm, 0,
                   db2, 0, 1, buf + OFF_Y, 0, 1, MT, Dm, Ff, 1);
    ln_k<<<MT, 128>>>(buf + OFF_H, dlng + 2 * Dm, dlnb + 2 * Dm, buf + OFF_SOUT);
    if ((size_t)out_size >= 2 * MTD)
        cudaMemcpyAsync(dout + MTD, buf + OFF_SOUT, MTD * sizeof(float),
                        cudaMemcpyDeviceToDevice);

    // ---- xg (cat slice 0) from t_out
    tt_k<<<Bq * Nn, 256>>>(buf + OFF_MEM, ttw, ttb, buf + OFF_CAT);

    // ---- s_out2 = s_out @ ts_w^T + ts_b  -> (B*L, N, N)
    launch_gemm<1>(buf + OFF_SOUT, Dm, 0, 1, buf + OFF_TSWT, Nn, 0, 1,
                   buf + OFF_S2, Nn, 0, tsb, 0, 1, nullptr, 0, 1, MT, Nn, Dm, 1);

    // ---- static graph convs
    const size_t catStride = (size_t)CC * Nn;
    const size_t sliceSz = (size_t)Dm * Nn;
    for (int s = 0; s < NGc; s++) {
        const float* As = buf + OFF_ADJ + (size_t)s * Nn * Nn;
        launch_gemm<0>(buf + OFF_CAT, Nn, catStride, BIG, As, Nn, 0, 1,
                       buf + OFF_CAT + (1 + 2 * s) * sliceSz, Nn, catStride,
                       nullptr, 0, 1, nullptr, 0, 1, Dm, Nn, Nn, Bq * Ol);
        launch_gemm<0>(buf + OFF_CAT + (1 + 2 * s) * sliceSz, Nn, catStride, BIG,
                       As, Nn, 0, 1,
                       buf + OFF_CAT + (2 + 2 * s) * sliceSz, Nn, catStride,
                       nullptr, 0, 1, nullptr, 0, 1, Dm, Nn, Nn, Bq * Ol);
    }
    // ---- adaptive graph convs
    launch_gemm<0>(buf + OFF_CAT, Nn, catStride, BIG,
                   buf + OFF_S2, Nn, (size_t)Nn * Nn, BIG,
                   buf + OFF_CAT + 7 * sliceSz, Nn, catStride,
                   nullptr, 0, 1, nullptr, 0, 1, Dm, Nn, Nn, Bq * Ol);
    launch_gemm<0>(buf + OFF_CAT + 7 * sliceSz, Nn, catStride, BIG,
                   buf + OFF_S2, Nn, (size_t)Nn * Nn, BIG,
                   buf + OFF_CAT + 8 * sliceSz, Nn, catStride,
                   nullptr, 0, 1, nullptr, 0, 1, Dm, Nn, Nn, Bq * Ol);

    // ---- GCN
    launch_gemm<5>(gw, CC, (size_t)Dm * CC, Ol,
                   buf + OFF_CAT, Nn, catStride, BIG,
                   dout, Dm, (size_t)Nn * Dm,
                   buf + OFF_SCALE, Dm, Ol,
                   buf + OFF_SHIFT, Dm, Ol,
                   Dm, Nn, CC, Bq * Ol);
}

// round 4
// speedup vs baseline: 3.2182x; 1.5168x over previous
#include <cuda_runtime.h>
#include <cuda_bf16.h>
#include <math.h>

// ---------------------------------------------------------------------------
// Problem constants
// ---------------------------------------------------------------------------
constexpr int Bq = 8, Lq = 12, Nn = 207, Dm = 512, Hh = 8, Ff = 2048;
constexpr int Ol = 12, NGc = 3;
constexpr int T  = Lq * Nn;          // 2484
constexpr int MT = Bq * T;           // 19872 rows
constexpr int E  = Dm / Hh;          // 64
constexpr int CC = Dm * (NGc + 1) * 2 + Dm;  // 4608
constexpr int NP = 208;              // padded N/K for graph stage
constexpr int KVS = 4;               // kv split factor
constexpr int TCH = T / KVS;         // 621

constexpr size_t MTD = (size_t)MT * Dm;

// buffer offsets (floats)
constexpr size_t OFF_XR   = 0;
constexpr size_t OFF_STR  = 1 * MTD;
constexpr size_t OFF_Q    = 2 * MTD;
constexpr size_t OFF_K    = 3 * MTD;
constexpr size_t OFF_V    = 4 * MTD;
constexpr size_t OFF_ATTN = 5 * MTD;
constexpr size_t OFF_H    = 6 * MTD;
constexpr size_t OFF_Y    = 7 * MTD;
constexpr size_t OFF_YR   = 8 * MTD;
constexpr size_t OFF_MEM  = 9 * MTD;
constexpr size_t OFF_MEMR = 10 * MTD;
constexpr size_t OFF_SOUT = 11 * MTD;
constexpr size_t OFF_SOUTR= 12 * MTD;
constexpr size_t OFF_FFN  = 13 * MTD;                 // 4*MTD
constexpr size_t OFF_WEQ  = 17 * MTD;                 // 4*512*512
constexpr size_t SZ_W4    = (size_t)4 * Dm * Dm;      // 1048576
constexpr size_t OFF_WDS  = OFF_WEQ + SZ_W4;
constexpr size_t OFF_WDC  = OFF_WDS + SZ_W4;
constexpr size_t OFF_WE1  = OFF_WDC + SZ_W4;
constexpr size_t OFF_WE2  = OFF_WE1 + (size_t)Dm * Ff;
constexpr size_t OFF_WD1  = OFF_WE2 + (size_t)Dm * Ff;
constexpr size_t OFF_WD2  = OFF_WD1 + (size_t)Dm * Ff;
constexpr size_t OFF_WG   = OFF_WD2 + (size_t)Dm * Ff;
constexpr size_t SZ_WG    = (size_t)Ol * Dm * CC;     // 28311552
constexpr size_t OFF_TSWT = OFF_WG + SZ_WG;           // 512 x 208
constexpr size_t OFF_ADJ  = OFF_TSWT + (size_t)Dm * NP;     // 3 x 208 x 208
constexpr size_t OFF_SCALE= OFF_ADJ + (size_t)NGc * NP * NP;
constexpr size_t OFF_SHIFT= OFF_SCALE + (size_t)Ol * Dm;
constexpr size_t OFF_KVP  = OFF_SHIFT + (size_t)Ol * Dm;
constexpr size_t OFF_KSP  = OFF_KVP + (size_t)KVS * 64 * E * E;
constexpr size_t OFF_KV   = OFF_KSP + (size_t)KVS * 64 * E;
constexpr size_t OFF_KSUM = OFF_KV + (size_t)64 * E * E;
constexpr size_t OFF_S2   = OFF_KSUM + (size_t)64 * E;      // MT x 208
constexpr size_t OFF_CAT  = OFF_S2 + (size_t)MT * NP;       // 96 x 4608 x 208
constexpr size_t OFF_SLACK= OFF_CAT + (size_t)Bq * Ol * CC * NP;
constexpr size_t TOTAL    = OFF_SLACK + 4096;

__device__ __align__(16) float g_buf[TOTAL];

__device__ __forceinline__ unsigned f2tf(float x) {
    unsigned r;
    asm("cvt.rna.tf32.f32 %0, %1;" : "=r"(r) : "f"(x));
    return r;
}
__device__ __forceinline__ float rtf(float x) { return __uint_as_float(f2tf(x)); }
__device__ __forceinline__ unsigned fbits(float x) { return __float_as_uint(x); }

// ---------------------------------------------------------------------------
// TF32 tensor-core batched GEMM with cp.async 4-stage pipeline.
// Inputs MUST be pre-rounded to tf32. A: MxK row-major, B: KxN row-major.
// K must be a multiple of 16. KB: B rows >= KB are zero-filled.
// Block 128x128, BK=16, 8 warps (2m x 4n), warp tile 64x32, m16n8k8.tf32.
// EPI: 0 none | 1 +bias[n] | 2 +bias[n],elu+1 | 3 +bias[n],gelu(tanh)
//      4 +bias[n]+res[m,n] | 5 val*P1[m]+P2[m], store C[n*ldc+m]
// RND: round stored values to tf32 (for values feeding later GEMMs).
// ---------------------------------------------------------------------------
constexpr int STAGES = 4;
constexpr int ASTR = 20;              // A smem row stride (floats)
constexpr int BSTR = 132;             // B smem row stride (floats)
constexpr int ASZ = 128 * ASTR;       // 2560 floats / stage
constexpr int BSZ = 16 * BSTR;        // 2112 floats / stage
constexpr size_t GSMEM = (size_t)STAGES * (ASZ + BSZ) * 4;   // 74752 B

template <int EPI, bool RND>
__global__ void __launch_bounds__(256, 2)
gemm_k(const float* __restrict__ A, int lda, size_t sA_, int mA,
       const float* __restrict__ Bm, int ldb, size_t sB_, int mB,
       float* __restrict__ C, int ldc, size_t sC,
       const float* __restrict__ P1, size_t sP1, int mP1,
       const float* __restrict__ P2, size_t sP2, int mP2,
       int M, int N, int K, int KB)
{
    extern __shared__ float smem[];
    float* sA = smem;
    float* sB = smem + (size_t)STAGES * ASZ;

    int bz = blockIdx.z;
    A  += (size_t)(bz % mA) * sA_;
    Bm += (size_t)(bz % mB) * sB_;
    C  += (size_t)bz * sC;
    const float* p1 = (EPI > 0) ? P1 + (size_t)(bz % mP1) * sP1 : nullptr;
    const float* p2 = (EPI == 4 || EPI == 5) ? P2 + (size_t)(bz % mP2) * sP2 : nullptr;

    int tid  = threadIdx.x;
    int lane = tid & 31, wid = tid >> 5;
    int wm = wid & 1, wn = wid >> 1;
    int g = lane >> 2, t = lane & 3;
    int m0 = blockIdx.y * 128;
    int n0 = blockIdx.x * 128;

    // ---- loader setup: 2 chunks of A (16B) + 2 chunks of B per thread
    int c0 = tid, c1 = tid + 256;
    int ar0 = c0 >> 2, ak0 = (c0 & 3) << 2;
    int ar1 = c1 >> 2, ak1 = (c1 & 3) << 2;
    int bk0 = c0 >> 5, bn0 = (c0 & 31) << 2;
    int bk1 = c1 >> 5, bn1 = (c1 & 31) << 2;

    bool am0 = (m0 + ar0) < M, am1 = (m0 + ar1) < M;
    int arc0 = am0 ? (m0 + ar0) : (M - 1);
    int arc1 = am1 ? (m0 + ar1) : (M - 1);
    const float* aS0 = A + (size_t)arc0 * lda + ak0;
    const float* aS1 = A + (size_t)arc1 * lda + ak1;
    const float* bS0 = Bm + (size_t)bk0 * ldb + n0 + bn0;
    const float* bS1 = Bm + (size_t)bk1 * ldb + n0 + bn1;

    unsigned sbase = (unsigned)__cvta_generic_to_shared(smem);
    unsigned aD0 = sbase + (ar0 * ASTR + ak0) * 4;
    unsigned aD1 = sbase + (ar1 * ASTR + ak1) * 4;
    unsigned bD0 = sbase + (STAGES * ASZ + bk0 * BSTR + bn0) * 4;
    unsigned bD1 = sbase + (STAGES * ASZ + bk1 * BSTR + bn1) * 4;

    auto COPY = [&](int s, int k0) {
        unsigned pa0 = am0 ? 16u : 0u;
        unsigned pa1 = am1 ? 16u : 0u;
        unsigned pb0 = (k0 + bk0 < KB) ? 16u : 0u;
        unsigned pb1 = (k0 + bk1 < KB) ? 16u : 0u;
        const float* a0 = aS0 + k0;
        const float* a1 = aS1 + k0;
        const float* b0 = bS0 + (size_t)k0 * ldb;
        const float* b1 = bS1 + (size_t)k0 * ldb;
        unsigned so = s * (ASZ * 4);
        unsigned sob = s * (BSZ * 4);
        asm volatile("cp.async.cg.shared.global [%0], [%1], 16, %2;\n"
                     :: "r"(aD0 + so), "l"(a0), "r"(pa0));
        asm volatile("cp.async.cg.shared.global [%0], [%1], 16, %2;\n"
                     :: "r"(aD1 + so), "l"(a1), "r"(pa1));
        asm volatile("cp.async.cg.shared.global [%0], [%1], 16, %2;\n"
                     :: "r"(bD0 + sob), "l"(b0), "r"(pb0));
        asm volatile("cp.async.cg.shared.global [%0], [%1], 16, %2;\n"
                     :: "r"(bD1 + sob), "l"(b1), "r"(pb1));
    };

    // ---- fragment bases (immediate offsets thereafter)
    const float* aBase[4];
    const float* bBase[4];
#pragma unroll
    for (int mt = 0; mt < 4; mt++) {
        int rm = wm * 64 + mt * 16 + g;
        aBase[mt] = sA + rm * ASTR + t;
    }
#pragma unroll
    for (int nt = 0; nt < 4; nt++) {
        int cn = wn * 32 + nt * 8 + g;
        bBase[nt] = sB + t * BSTR + cn;
    }

    float acc[16][4];
#pragma unroll
    for (int i = 0; i < 16; i++)
#pragma unroll
        for (int j = 0; j < 4; j++) acc[i][j] = 0.f;

    int nk = K >> 4;   // K multiple of 16 guaranteed

    // prologue: STAGES-1 stages
#pragma unroll
    for (int s = 0; s < STAGES - 1; s++) {
        if (s < nk) COPY(s, s << 4);
        asm volatile("cp.async.commit_group;\n");
    }

    int cur = 0;
    for (int kb = 0; kb < nk; kb++) {
        asm volatile("cp.async.wait_group %0;\n" :: "n"(STAGES - 2));
        __syncthreads();
        if (kb + STAGES - 1 < nk) COPY((kb + STAGES - 1) & (STAGES - 1), (kb + STAGES - 1) << 4);
        asm volatile("cp.async.commit_group;\n");

        const float* ab0 = aBase[0] + cur * ASZ;
        const float* ab1 = aBase[1] + cur * ASZ;
        const float* ab2 = aBase[2] + cur * ASZ;
        const float* ab3 = aBase[3] + cur * ASZ;
        const float* bb0 = bBase[0] + cur * BSZ;
        const float* bb1 = bBase[1] + cur * BSZ;
        const float* bb2 = bBase[2] + cur * BSZ;
        const float* bb3 = bBase[3] + cur * BSZ;
        const float* ab[4] = {ab0, ab1, ab2, ab3};
        const float* bb[4] = {bb0, bb1, bb2, bb3};

#pragma unroll
        for (int ks = 0; ks < 2; ks++) {
            const int ko = ks * 8;
            const int kbo = ks * 1056;
            unsigned af[4][4], bf[4][2];
#pragma unroll
            for (int mt = 0; mt < 4; mt++) {
                af[mt][0] = fbits(ab[mt][ko]);
                af[mt][1] = fbits(ab[mt][ko + 160]);
                af[mt][2] = fbits(ab[mt][ko + 4]);
                af[mt][3] = fbits(ab[mt][ko + 164]);
            }
#pragma unroll
            for (int nt = 0; nt < 4; nt++) {
                bf[nt][0] = fbits(bb[nt][kbo]);
                bf[nt][1] = fbits(bb[nt][kbo + 528]);
            }
#pragma unroll
            for (int mt = 0; mt < 4; mt++)
#pragma unroll
                for (int nt = 0; nt < 4; nt++) {
                    float* c = acc[mt * 4 + nt];
                    asm volatile(
                        "mma.sync.aligned.m16n8k8.row.col.f32.tf32.tf32.f32 "
                        "{%0,%1,%2,%3}, {%4,%5,%6,%7}, {%8,%9}, {%0,%1,%2,%3};"
                        : "+f"(c[0]), "+f"(c[1]), "+f"(c[2]), "+f"(c[3])
                        : "r"(af[mt][0]), "r"(af[mt][1]), "r"(af[mt][2]), "r"(af[mt][3]),
                          "r"(bf[nt][0]), "r"(bf[nt][1]));
                }
        }
        cur = (cur + 1) & (STAGES - 1);
    }

    // epilogue
#pragma unroll
    for (int mt = 0; mt < 4; mt++)
#pragma unroll
        for (int nt = 0; nt < 4; nt++) {
            float* c = acc[mt * 4 + nt];
#pragma unroll
            for (int i = 0; i < 4; i++) {
                int m = m0 + wm * 64 + mt * 16 + g + (i >> 1) * 8;
                int n = n0 + wn * 32 + nt * 8 + 2 * t + (i & 1);
                if (m >= M || n >= N) continue;
                float v = c[i];
                if (EPI >= 1 && EPI <= 4) v += p1[n];
                if (EPI == 2) v = (v > 0.f) ? v + 1.f : expf(v);   // elu(x)+1
                if (EPI == 3) {
                    float cu = v * v * v;
                    v = 0.5f * v * (1.f + tanhf(0.7978845608028654f * (v + 0.044715f * cu)));
                }
                if (EPI == 4) v += p2[(size_t)m * ldc + n];
                if (EPI == 5) {
                    v = v * p1[m] + p2[m];
                    C[(size_t)n * ldc + m] = v;
                } else {
                    C[(size_t)m * ldc + n] = RND ? rtf(v) : v;
                }
            }
        }
}

template <int EPI, bool RND>
static void launch_gemm(const float* A, int lda, size_t sA, int mA,
                        const float* B, int ldb, size_t sB, int mB,
                        float* C, int ldc, size_t sC,
                        const float* P1, size_t sP1, int mP1,
                        const float* P2, size_t sP2, int mP2,
                        int M, int N, int K, int KB, int batch)
{
    cudaFuncSetAttribute(gemm_k<EPI, RND>,
                         cudaFuncAttributeMaxDynamicSharedMemorySize, (int)GSMEM);
    dim3 grid((N + 127) / 128, (M + 127) / 128, batch);
    gemm_k<EPI, RND><<<grid, 256, GSMEM>>>(A, lda, sA, mA, B, ldb, sB, mB, C, ldc, sC,
                                           P1, sP1, mP1, P2, sP2, mP2, M, N, K, KB);
}

// ---------------------------------------------------------------------------
// Linear attention internals (fp32, unrounded inputs)
// ---------------------------------------------------------------------------
__global__ void __launch_bounds__(256)
kv_part_k(const float* __restrict__ kf, const float* __restrict__ vv,
          float* __restrict__ kvp, float* __restrict__ ksp)
{
    int bh = blockIdx.x;
    int sp = blockIdx.y;
    int b = bh >> 3, h = bh & 7;
    int ts = sp * TCH, te = ts + TCH;
    const float* kbase = kf + (size_t)b * T * Dm + h * E;
    const float* vbase = vv + (size_t)b * T * Dm + h * E;
    __shared__ float ks[16][64];
    __shared__ float vs[16][64];
    int tid = threadIdx.x;
    int tx = tid & 15, ty = tid >> 4;
    float acc[4][4] = {};
    float csum = 0.f;
    for (int t0 = ts; t0 < te; t0 += 16) {
#pragma unroll
        for (int i = 0; i < 4; i++) {
            int idx = tid + i * 256;
            int rr = idx >> 6, cc = idx & 63;
            int gt = t0 + rr;
            bool ok = gt < te;
            ks[rr][cc] = ok ? kbase[(size_t)gt * Dm + cc] : 0.f;
            vs[rr][cc] = ok ? vbase[(size_t)gt * Dm + cc] : 0.f;
        }
        __syncthreads();
#pragma unroll
        for (int r = 0; r < 16; r++) {
            float a[4], bb[4];
#pragma unroll
            for (int i = 0; i < 4; i++) a[i] = ks[r][tx * 4 + i];
#pragma unroll
            for (int j = 0; j < 4; j++) bb[j] = vs[r][ty * 4 + j];
#pragma unroll
            for (int i = 0; i < 4; i++)
#pragma unroll
                for (int j = 0; j < 4; j++)
                    acc[i][j] = fmaf(a[i], bb[j], acc[i][j]);
        }
        if (tid < 64) {
#pragma unroll
            for (int r = 0; r < 16; r++) csum += ks[r][tid];
        }
        __syncthreads();
    }
    float* kvb = kvp + ((size_t)sp * 64 + bh) * E * E;
#pragma unroll
    for (int i = 0; i < 4; i++)
#pragma unroll
        for (int j = 0; j < 4; j++)
            kvb[(tx * 4 + i) * E + ty * 4 + j] = acc[i][j];
    if (tid < 64) ksp[((size_t)sp * 64 + bh) * E + tid] = csum;
}

__global__ void __launch_bounds__(256)
kv_reduce_k(const float* __restrict__ kvp, const float* __restrict__ ksp,
            float* __restrict__ kv, float* __restrict__ ksum)
{
    const int NKV = 64 * E * E;
    int i = blockIdx.x * 256 + threadIdx.x;
    if (i < NKV) {
        float s = 0.f;
#pragma unroll
        for (int sp = 0; sp < KVS; sp++) s += kvp[(size_t)sp * NKV + i];
        kv[i] = s;
    } else if (i < NKV + 64 * E) {
        int j = i - NKV;
        float s = 0.f;
#pragma unroll
        for (int sp = 0; sp < KVS; sp++) s += ksp[(size_t)sp * 64 * E + j];
        ksum[j] = s;
    }
}

// o = (qf@kv)*z ; stores tf32-rounded (feeds output-projection GEMM)
__global__ void __launch_bounds__(256)
attn_o_k(const float* __restrict__ qf, const float* __restrict__ kv,
         const float* __restrict__ ksum, float* __restrict__ out)
{
    int bh = blockIdx.x;
    int b = bh >> 3, h = bh & 7;
    int t0 = blockIdx.y * 64;
    const float* qbase = qf + (size_t)b * T * Dm + h * E;
    __shared__ float qs[64][64];
    __shared__ float kvs[64][65];
    __shared__ float kss[64];
    __shared__ float zs[64];
    int tid = threadIdx.x;
    int tx = tid & 15, ty = tid >> 4;
#pragma unroll
    for (int i = 0; i < 16; i++) {
        int idx = tid + i * 256;
        int r = idx >> 6, c = idx & 63;
        kvs[r][c] = kv[(size_t)bh * E * E + idx];
        int gt = t0 + r;
        qs[r][c] = (gt < T) ? qbase[(size_t)gt * Dm + c] : 0.f;
    }
    if (tid < 64) kss[tid] = ksum[(size_t)bh * E + tid];
    __syncthreads();
    if (tid < 64) {
        float s = 0.f;
#pragma unroll
        for (int e = 0; e < 64; e++) s = fmaf(qs[tid][e], kss[e], s);
        zs[tid] = 1.f / (s + 1e-6f);
    }
    __syncthreads();
    float acc[4][4] = {};
#pragma unroll
    for (int e = 0; e < 64; e++) {
        float a[4], bb[4];
#pragma unroll
        for (int i = 0; i < 4; i++) a[i] = qs[ty * 4 + i][e];
#pragma unroll
        for (int j = 0; j < 4; j++) bb[j] = kvs[e][tx * 4 + j];
#pragma unroll
        for (int i = 0; i < 4; i++)
#pragma unroll
            for (int j = 0; j < 4; j++)
                acc[i][j] = fmaf(a[i], bb[j], acc[i][j]);
    }
#pragma unroll
    for (int i = 0; i < 4; i++) {
        int t = t0 + ty * 4 + i;
        if (t >= T) continue;
        float z = zs[ty * 4 + i];
#pragma unroll
        for (int j = 0; j < 4; j++)
            out[((size_t)b * T + t) * Dm + h * E + tx * 4 + j] = rtf(acc[i][j] * z);
    }
}

// ---------------------------------------------------------------------------
// LayerNorm over D=512; writes full-precision (outp) and tf32-rounded (outr)
// ---------------------------------------------------------------------------
__global__ void __launch_bounds__(128)
ln_k(const float* __restrict__ x, const float* __restrict__ g,
     const float* __restrict__ bvec, float* __restrict__ outp,
     float* __restrict__ outr)
{
    int r = blockIdx.x;
    int t = threadIdx.x;
    const float4* xr = (const float4*)(x + (size_t)r * Dm);
    float4 v = xr[t];
    float s = v.x + v.y + v.z + v.w;
    float q = v.x * v.x + v.y * v.y + v.z * v.z + v.w * v.w;
#pragma unroll
    for (int o = 16; o > 0; o >>= 1) {
        s += __shfl_down_sync(0xffffffffu, s, o);
        q += __shfl_down_sync(0xffffffffu, q, o);
    }
    __shared__ float ss[4], qq[4], mv[2];
    int w = t >> 5, l = t & 31;
    if (l == 0) { ss[w] = s; qq[w] = q; }
    __syncthreads();
    if (t == 0) {
        float S = ss[0] + ss[1] + ss[2] + ss[3];
        float Q = qq[0] + qq[1] + qq[2] + qq[3];
        float m = S * (1.f / 512.f);
        float var = Q * (1.f / 512.f) - m * m;
        mv[0] = m;
        mv[1] = rsqrtf(var + 1e-5f);
    }
    __syncthreads();
    float m = mv[0], inv = mv[1];
    float4 gg = ((const float4*)g)[t];
    float4 bb = ((const float4*)bvec)[t];
    float4 o4;
    o4.x = (v.x - m) * inv * gg.x + bb.x;
    o4.y = (v.y - m) * inv * gg.y + bb.y;
    o4.z = (v.z - m) * inv * gg.z + bb.z;
    o4.w = (v.w - m) * inv * gg.w + bb.w;
    ((float4*)(outp + (size_t)r * Dm))[t] = o4;
    float4 r4;
    r4.x = rtf(o4.x); r4.y = rtf(o4.y); r4.z = rtf(o4.z); r4.w = rtf(o4.w);
    ((float4*)(outr + (size_t)r * Dm))[t] = r4;
}

// ---------------------------------------------------------------------------
// tt: cat slice0 row d col n (stride NP), rounded
// ---------------------------------------------------------------------------
__global__ void __launch_bounds__(256)
tt_k(const float* __restrict__ tout, const float* __restrict__ ttw,
     const float* __restrict__ ttb, float* __restrict__ cat)
{
    int bn = blockIdx.x;
    int b = bn / Nn, n = bn % Nn;
    __shared__ float xs[12][512];
    __shared__ float w[144];
    int tid = threadIdx.x;
    if (tid < 144) w[tid] = ttw[tid];
    for (int l = 0; l < 12; l++)
        for (int d = tid; d < 512; d += 256)
            xs[l][d] = tout[(((size_t)b * Lq + l) * Nn + n) * Dm + d];
    __syncthreads();
    for (int od = tid; od < 12 * 512; od += 256) {
        int o = od >> 9, d = od & 511;
        float s = ttb[o];
#pragma unroll
        for (int l = 0; l < 12; l++) s = fmaf(w[o * 12 + l], xs[l][d], s);
        cat[(((size_t)b * Ol + o) * CC + d) * NP + n] = rtf(s);
    }
}

// ---------------------------------------------------------------------------
// Prep kernels (round everything feeding GEMMs)
// ---------------------------------------------------------------------------
__global__ void round_k(const float* __restrict__ src, float* __restrict__ dst, int n)
{
    int i = blockIdx.x * 256 + threadIdx.x;
    if (i < n) dst[i] = rtf(src[i]);
}
__global__ void prep_tswT(const float* __restrict__ tsw, float* __restrict__ outT)
{
    int i = blockIdx.x * 256 + threadIdx.x;
    if (i < Nn * Dm) {
        int m = i / Dm, d = i % Dm;
        outT[(size_t)d * NP + m] = rtf(tsw[i]);
    }
}
__global__ void prep_adj(const float* __restrict__ adj, float* __restrict__ out)
{
    int i = blockIdx.x * 256 + threadIdx.x;
    if (i < NGc * Nn * Nn) {
        int s = i / (Nn * Nn);
        int r = (i / Nn) % Nn, c = i % Nn;
        out[(size_t)s * NP * NP + r * NP + c] = rtf(adj[((size_t)r * Nn + c) * NGc + s]);
    }
}
__global__ void prep_ss(const float* __restrict__ gb, const float* __restrict__ bng,
                        const float* __restrict__ bnb, float* __restrict__ sc,
                        float* __restrict__ sh)
{
    int i = blockIdx.x * 256 + threadIdx.x;
    if (i < Ol * Dm) {
        sc[i] = bng[i];
        sh[i] = gb[i] * bng[i] + bnb[i];
    }
}

// ---------------------------------------------------------------------------
// Host-side composition
// ---------------------------------------------------------------------------
static void run_attention(const float* xqr, const float* xkvr,
                          const float* w, const float* bvec,
                          const float* res, float* buf, float* out)
{
    float* q  = buf + OFF_Q;
    float* k  = buf + OFF_K;
    float* v  = buf + OFF_V;
    float* kv = buf + OFF_KV;
    float* ks = buf + OFF_KSUM;
    float* at = buf + OFF_ATTN;
    launch_gemm<2, false>(xqr,  Dm, 0, 1, w,              Dm, 0, 1, q, Dm, 0,
                          bvec,          0, 1, nullptr, 0, 1, MT, Dm, Dm, Dm, 1);
    launch_gemm<2, false>(xkvr, Dm, 0, 1, w + Dm * Dm,    Dm, 0, 1, k, Dm, 0,
                          bvec + Dm,     0, 1, nullptr, 0, 1, MT, Dm, Dm, Dm, 1);
    launch_gemm<1, false>(xkvr, Dm, 0, 1, w + 2 * Dm * Dm, Dm, 0, 1, v, Dm, 0,
                          bvec + 2 * Dm, 0, 1, nullptr, 0, 1, MT, Dm, Dm, Dm, 1);
    kv_part_k<<<dim3(Bq * Hh, KVS), 256>>>(k, v, buf + OFF_KVP, buf + OFF_KSP);
    kv_reduce_k<<<(64 * E * E + 64 * E + 255) / 256, 256>>>(buf + OFF_KVP, buf + OFF_KSP, kv, ks);
    attn_o_k<<<dim3(Bq * Hh, (T + 63) / 64), 256>>>(q, kv, ks, at);
    launch_gemm<4, false>(at, Dm, 0, 1, w + 3 * Dm * Dm, Dm, 0, 1, out, Dm, 0,
                          bvec + 3 * Dm, 0, 1, res, 0, 1, MT, Dm, Dm, Dm, 1);
}

extern "C" void kernel_launch(void* const* d_in, const int* in_sizes, int n_in,
                              void* d_out, int out_size)
{
    const float* x    = (const float*)d_in[0];
    const float* st   = (const float*)d_in[1];
    const float* adj  = (const float*)d_in[3];
    const float* eqw  = (const float*)d_in[4];
    const float* eqb  = (const float*)d_in[5];
    const float* ew1  = (const float*)d_in[6];
    const float* eb1  = (const float*)d_in[7];
    const float* ew2  = (const float*)d_in[8];
    const float* eb2  = (const float*)d_in[9];
    const float* elng = (const float*)d_in[10];
    const float* elnb = (const float*)d_in[11];
    const float* dsw  = (const float*)d_in[12];
    const float* dsb  = (const float*)d_in[13];
    const float* dcw  = (const float*)d_in[14];
    const float* dcb  = (const float*)d_in[15];
    const float* dw1  = (const float*)d_in[16];
    const float* db1  = (const float*)d_in[17];
    const float* dw2  = (const float*)d_in[18];
    const float* db2  = (const float*)d_in[19];
    const float* dlng = (const float*)d_in[20];
    const float* dlnb = (const float*)d_in[21];
    const float* ttw  = (const float*)d_in[22];
    const float* ttb  = (const float*)d_in[23];
    const float* tsw  = (const float*)d_in[24];
    const float* tsb  = (const float*)d_in[25];
    const float* gw   = (const float*)d_in[26];
    const float* gb   = (const float*)d_in[27];
    const float* bng  = (const float*)d_in[28];
    const float* bnb  = (const float*)d_in[29];

    float* buf = nullptr;
    cudaGetSymbolAddress((void**)&buf, g_buf);
    float* dout = (float*)d_out;

    const int BIG = 1 << 30;
    auto RND = [&](const float* s, float* d, size_t n) {
        round_k<<<(int)((n + 255) / 256), 256>>>(s, d, (int)n);
    };

    // ---- prep: round all GEMM operands
    RND(x, buf + OFF_XR, MTD);
    RND(st, buf + OFF_STR, MTD);
    RND(eqw, buf + OFF_WEQ, SZ_W4);
    RND(dsw, buf + OFF_WDS, SZ_W4);
    RND(dcw, buf + OFF_WDC, SZ_W4);
    RND(ew1, buf + OFF_WE1, (size_t)Dm * Ff);
    RND(ew2, buf + OFF_WE2, (size_t)Dm * Ff);
    RND(dw1, buf + OFF_WD1, (size_t)Dm * Ff);
    RND(dw2, buf + OFF_WD2, (size_t)Dm * Ff);
    RND(gw, buf + OFF_WG, SZ_WG);
    prep_tswT<<<(Nn * Dm + 255) / 256, 256>>>(tsw, buf + OFF_TSWT);
    prep_adj<<<(NGc * Nn * Nn + 255) / 256, 256>>>(adj, buf + OFF_ADJ);
    prep_ss<<<(Ol * Dm + 255) / 256, 256>>>(gb, bng, bnb, buf + OFF_SCALE, buf + OFF_SHIFT);

    // ---- encoder
    run_attention(buf + OFF_XR, buf + OFF_XR, buf + OFF_WEQ, eqb, x, buf, buf + OFF_H);
    ln_k<<<MT, 128>>>(buf + OFF_H, elng, elnb, buf + OFF_Y, buf + OFF_YR);
    launch_gemm<3, true>(buf + OFF_YR, Dm, 0, 1, buf + OFF_WE1, Ff, 0, 1, buf + OFF_FFN, Ff, 0,
                         eb1, 0, 1, nullptr, 0, 1, MT, Ff, Dm, Dm, 1);
    launch_gemm<4, false>(buf + OFF_FFN, Ff, 0, 1, buf + OFF_WE2, Dm, 0, 1, buf + OFF_H, Dm, 0,
                          eb2, 0, 1, buf + OFF_Y, 0, 1, MT, Dm, Ff, Ff, 1);
    ln_k<<<MT, 128>>>(buf + OFF_H, elng + Dm, elnb + Dm, buf + OFF_MEM, buf + OFF_MEMR);

    // ---- decoder self
    run_attention(buf + OFF_STR, buf + OFF_STR, buf + OFF_WDS, dsb, st, buf, buf + OFF_H);
    ln_k<<<MT, 128>>>(buf + OFF_H, dlng, dlnb, buf + OFF_Y, buf + OFF_YR);
    // ---- decoder cross
    run_attention(buf + OFF_YR, buf + OFF_MEMR, buf + OFF_WDC, dcb, buf + OFF_Y, buf, buf + OFF_H);
    ln_k<<<MT, 128>>>(buf + OFF_H, dlng + Dm, dlnb + Dm, buf + OFF_Y, buf + OFF_YR);
    // ---- decoder ffn + final ln -> s_out
    launch_gemm<3, true>(buf + OFF_YR, Dm, 0, 1, buf + OFF_WD1, Ff, 0, 1, buf + OFF_FFN, Ff, 0,
                         db1, 0, 1, nullptr, 0, 1, MT, Ff, Dm, Dm, 1);
    launch_gemm<4, false>(buf + OFF_FFN, Ff, 0, 1, buf + OFF_WD2, Dm, 0, 1, buf + OFF_H, Dm, 0,
                          db2, 0, 1, buf + OFF_Y, 0, 1, MT, Dm, Ff, Ff, 1);
    ln_k<<<MT, 128>>>(buf + OFF_H, dlng + 2 * Dm, dlnb + 2 * Dm, buf + OFF_SOUT, buf + OFF_SOUTR);
    if ((size_t)out_size >= 2 * MTD)
        cudaMemcpyAsync(dout + MTD, buf + OFF_SOUT, MTD * sizeof(float),
                        cudaMemcpyDeviceToDevice);

    // ---- xg (cat slice 0) from t_out (plain)
    tt_k<<<Bq * Nn, 256>>>(buf + OFF_MEM, ttw, ttb, buf + OFF_CAT);

    // ---- s_out2 = s_out @ ts_w^T + ts_b -> S2 (MT x NP, rounded)
    launch_gemm<1, true>(buf + OFF_SOUTR, Dm, 0, 1, buf + OFF_TSWT, NP, 0, 1,
                         buf + OFF_S2, NP, 0, tsb, 0, 1, nullptr, 0, 1,
                         MT, Nn, Dm, Dm, 1);

    // ---- static graph convs: per (b,o): X(512x207) @ A_s
    const size_t catStride = (size_t)CC * NP;
    const size_t sliceSz = (size_t)Dm * NP;
    for (int s = 0; s < NGc; s++) {
        const float* As = buf + OFF_ADJ + (size_t)s * NP * NP;
        launch_gemm<0, true>(buf + OFF_CAT, NP, catStride, BIG, As, NP, 0, 1,
                             buf + OFF_CAT + (1 + 2 * s) * sliceSz, NP, catStride,
                             nullptr, 0, 1, nullptr, 0, 1, Dm, Nn, NP, NP, Bq * Ol);
        launch_gemm<0, true>(buf + OFF_CAT + (1 + 2 * s) * sliceSz, NP, catStride, BIG,
                             As, NP, 0, 1,
                             buf + OFF_CAT + (2 + 2 * s) * sliceSz, NP, catStride,
                             nullptr, 0, 1, nullptr, 0, 1, Dm, Nn, NP, NP, Bq * Ol);
    }
    // ---- adaptive graph convs (B = S2 blocks; row 207 zero-filled via KB)
    launch_gemm<0, true>(buf + OFF_CAT, NP, catStride, BIG,
                         buf + OFF_S2, NP, (size_t)Nn * NP, BIG,
                         buf + OFF_CAT + 7 * sliceSz, NP, catStride,
                         nullptr, 0, 1, nullptr, 0, 1, Dm, Nn, NP, Nn, Bq * Ol);
    launch_gemm<0, true>(buf + OFF_CAT + 7 * sliceSz, NP, catStride, BIG,
                         buf + OFF_S2, NP, (size_t)Nn * NP, BIG,
                         buf + OFF_CAT + 8 * sliceSz, NP, catStride,
                         nullptr, 0, 1, nullptr, 0, 1, Dm, Nn, NP, Nn, Bq * Ol);

    // ---- GCN: W_o(512x4608) @ cat(4608x207); bn affine; store dts[b,o,n,d]
    launch_gemm<5, false>(buf + OFF_WG, CC, (size_t)Dm * CC, Ol,
                          buf + OFF_CAT, NP, catStride, BIG,
                          dout, Dm, (size_t)Nn * Dm,
                          buf + OFF_SCALE, Dm, Ol,
                          buf + OFF_SHIFT, Dm, Ol,
                          Dm, Nn, CC, CC, Bq * Ol);
}